// round 7
// baseline (speedup 1.0000x reference)
#include <cuda_runtime.h>
#include <cuda_bf16.h>
#include <cstdint>

#define NTHREADS 128
#define NROWS_T 3                     // rows per thread
#define ROWS_PER_BLOCK (NTHREADS * NROWS_T)   // 384
#define PFEAT 32
#define XS 385                        // x_s row stride (== 1 mod 32 -> conflict-free)

typedef unsigned long long u64;

// ---- shared-memory layout (floats); weight bases 16B-aligned ----
#define OFF_WB1T 0        // [32][64] (input-row p zeroed)
#define OFF_WB2T 2048     // [64][32]
#define OFF_WB3T 4096     // [32][32]
#define OFF_WB4T 5120     // [32][16]
#define OFF_WB5T 5632     // [16][8]
#define OFF_WA2T 5760     // [64][32]
#define OFF_WA3T 7808     // [32][16]
#define OFF_WA4T 8320     // [16][8]
#define OFF_WA1  8448     // 64
#define OFF_BA1  8512     // 64
#define OFF_BB1  8576     // 64
#define OFF_BB2  8640     // 32
#define OFF_BB3  8672     // 32
#define OFF_BB4  8704     // 16
#define OFF_BA2  8720     // 32
#define OFF_BA3  8752     // 16
#define OFF_BA4  8768     // 8
#define OFF_BB5  8776     // 8
#define OFF_WB6  8784     // 8
#define OFF_WA5  8792     // 8
#define OFF_BB6  8800     // 1
#define OFF_BA5  8804     // 1
#define W_TOT    8808
#define OFF_XS   8808     // x_s [32][XS]
#define SMEM_FLOATS (W_TOT + 32 * XS)

// ---- f32x2 packed helpers ----
__device__ __forceinline__ u64 pk2(float v) {
    u64 r; asm("mov.b64 %0, {%1, %1};" : "=l"(r) : "f"(v)); return r;
}
__device__ __forceinline__ void upk(float& lo, float& hi, u64 v) {
    asm("mov.b64 {%0, %1}, %2;" : "=f"(lo), "=f"(hi) : "l"(v));
}
__device__ __forceinline__ u64 f2fma(u64 a, u64 b, u64 c) {
    u64 d; asm("fma.rn.f32x2 %0, %1, %2, %3;" : "=l"(d) : "l"(a), "l"(b), "l"(c));
    return d;
}
__device__ __forceinline__ float fast_tanh(float x) {
    float r; asm("tanh.approx.f32 %0, %1;" : "=f"(r) : "f"(x)); return r;
}

// ===== packed->packed layer, 3 rows share weights; ACTIN: 0 none, 2 tanh on inputs =====
template<int IN, int OUT, int ACTIN>
__device__ __forceinline__ void layerP3(const float* __restrict__ Wt,
                                        const float* __restrict__ B,
                                        const u64* in0, const u64* in1, const u64* in2,
                                        u64* a0, u64* a1, u64* a2) {
#pragma unroll
    for (int o = 0; o < OUT / 2; o++) {
        u64 b = *reinterpret_cast<const u64*>(B + 2 * o);
        a0[o] = b; a1[o] = b; a2[o] = b;
    }
#pragma unroll
    for (int ip = 0; ip < IN / 2; ip++) {
        float e0, f0, e1, f1, e2, f2;
        upk(e0, f0, in0[ip]); upk(e1, f1, in1[ip]); upk(e2, f2, in2[ip]);
        if (ACTIN == 2) {
            e0 = fast_tanh(e0); f0 = fast_tanh(f0);
            e1 = fast_tanh(e1); f1 = fast_tanh(f1);
            e2 = fast_tanh(e2); f2 = fast_tanh(f2);
        }
        const u64 xa0 = pk2(e0), xb0 = pk2(f0);
        const u64 xa1 = pk2(e1), xb1 = pk2(f1);
        const u64 xa2 = pk2(e2), xb2 = pk2(f2);
        const float* wA = Wt + (2 * ip) * OUT;
        const float* wB = wA + OUT;
#pragma unroll
        for (int o = 0; o < OUT / 2; o += 2) {
            ulonglong2 wa = *reinterpret_cast<const ulonglong2*>(wA + 2 * o);
            a0[o]     = f2fma(wa.x, xa0, a0[o]);
            a1[o]     = f2fma(wa.x, xa1, a1[o]);
            a2[o]     = f2fma(wa.x, xa2, a2[o]);
            a0[o + 1] = f2fma(wa.y, xa0, a0[o + 1]);
            a1[o + 1] = f2fma(wa.y, xa1, a1[o + 1]);
            a2[o + 1] = f2fma(wa.y, xa2, a2[o + 1]);
            ulonglong2 wb = *reinterpret_cast<const ulonglong2*>(wB + 2 * o);
            a0[o]     = f2fma(wb.x, xb0, a0[o]);
            a1[o]     = f2fma(wb.x, xb1, a1[o]);
            a2[o]     = f2fma(wb.x, xb2, a2[o]);
            a0[o + 1] = f2fma(wb.y, xb0, a0[o + 1]);
            a1[o + 1] = f2fma(wb.y, xb1, a1[o + 1]);
            a2[o + 1] = f2fma(wb.y, xb2, a2[o + 1]);
        }
    }
}

// ===== final dot, 3 rows; ACTIN on packed inputs =====
template<int IN, int ACTIN>
__device__ __forceinline__ void dotP3(const float* __restrict__ W, float b,
                                      const u64* in0, const u64* in1, const u64* in2,
                                      float& r0, float& r1, float& r2) {
    float a0 = b, a1 = b, a2 = b;
#pragma unroll
    for (int ip = 0; ip < IN / 2; ip++) {
        float e0, f0, e1, f1, e2, f2;
        upk(e0, f0, in0[ip]); upk(e1, f1, in1[ip]); upk(e2, f2, in2[ip]);
        if (ACTIN == 2) {
            e0 = fast_tanh(e0); f0 = fast_tanh(f0);
            e1 = fast_tanh(e1); f1 = fast_tanh(f1);
            e2 = fast_tanh(e2); f2 = fast_tanh(f2);
        }
        const float w0 = W[2 * ip], w1 = W[2 * ip + 1];
        a0 = fmaf(w0, e0, a0); a0 = fmaf(w1, f0, a0);
        a1 = fmaf(w0, e1, a1); a1 = fmaf(w1, f1, a1);
        a2 = fmaf(w0, e2, a2); a2 = fmaf(w1, f2, a2);
    }
    r0 = a0; r1 = a1; r2 = a2;
}

// ===== fused B: layer1 32->64 (relu) streamed in CHUNKs into layer2 raw acc; x from smem =====
template<int CHUNK>
__device__ __forceinline__ void fusedB3(const float* __restrict__ Wt1,
                                        const float* __restrict__ B1,
                                        const float* __restrict__ Wt2,
                                        const float* __restrict__ x0p,
                                        const float* __restrict__ x1p,
                                        const float* __restrict__ x2p,
                                        u64* a0, u64* a1, u64* a2) {
#pragma unroll
    for (int c = 0; c < 64; c += CHUNK) {
        u64 m0[CHUNK / 2], m1[CHUNK / 2], m2[CHUNK / 2];
#pragma unroll
        for (int j = 0; j < CHUNK / 2; j++) {
            u64 b = *reinterpret_cast<const u64*>(B1 + c + 2 * j);
            m0[j] = b; m1[j] = b; m2[j] = b;
        }
#pragma unroll
        for (int i = 0; i < 32; i++) {
            const u64 xx0 = pk2(x0p[i * XS]);
            const u64 xx1 = pk2(x1p[i * XS]);
            const u64 xx2 = pk2(x2p[i * XS]);
#pragma unroll
            for (int j = 0; j < CHUNK / 2; j += 2) {
                ulonglong2 w = *reinterpret_cast<const ulonglong2*>(Wt1 + i * 64 + c + 2 * j);
                m0[j]     = f2fma(w.x, xx0, m0[j]);
                m1[j]     = f2fma(w.x, xx1, m1[j]);
                m2[j]     = f2fma(w.x, xx2, m2[j]);
                m0[j + 1] = f2fma(w.y, xx0, m0[j + 1]);
                m1[j + 1] = f2fma(w.y, xx1, m1[j + 1]);
                m2[j + 1] = f2fma(w.y, xx2, m2[j + 1]);
            }
        }
#pragma unroll
        for (int j = 0; j < CHUNK / 2; j++) {
            float e0, f0, e1, f1, e2, f2;
            upk(e0, f0, m0[j]); upk(e1, f1, m1[j]); upk(e2, f2, m2[j]);
            e0 = fmaxf(e0, 0.0f); f0 = fmaxf(f0, 0.0f);
            e1 = fmaxf(e1, 0.0f); f1 = fmaxf(f1, 0.0f);
            e2 = fmaxf(e2, 0.0f); f2 = fmaxf(f2, 0.0f);
            const u64 pa0 = pk2(e0), pb0 = pk2(f0);
            const u64 pa1 = pk2(e1), pb1 = pk2(f1);
            const u64 pa2 = pk2(e2), pb2 = pk2(f2);
            const float* w2a = Wt2 + (c + 2 * j) * 32;
            const float* w2b = w2a + 32;
#pragma unroll
            for (int o = 0; o < 16; o += 2) {
                ulonglong2 wa = *reinterpret_cast<const ulonglong2*>(w2a + 2 * o);
                a0[o]     = f2fma(wa.x, pa0, a0[o]);
                a1[o]     = f2fma(wa.x, pa1, a1[o]);
                a2[o]     = f2fma(wa.x, pa2, a2[o]);
                a0[o + 1] = f2fma(wa.y, pa0, a0[o + 1]);
                a1[o + 1] = f2fma(wa.y, pa1, a1[o + 1]);
                a2[o + 1] = f2fma(wa.y, pa2, a2[o + 1]);
                ulonglong2 wb = *reinterpret_cast<const ulonglong2*>(w2b + 2 * o);
                a0[o]     = f2fma(wb.x, pb0, a0[o]);
                a1[o]     = f2fma(wb.x, pb1, a1[o]);
                a2[o]     = f2fma(wb.x, pb2, a2[o]);
                a0[o + 1] = f2fma(wb.y, pb0, a0[o + 1]);
                a1[o + 1] = f2fma(wb.y, pb1, a1[o + 1]);
                a2[o + 1] = f2fma(wb.y, pb2, a2[o + 1]);
            }
        }
    }
}

// ===== fused A head: elementwise (w*xs+b, relu) -> layer2 raw acc, 3 rows =====
__device__ __forceinline__ void fusedA3(const float* __restrict__ W1,
                                        const float* __restrict__ B1,
                                        const float* __restrict__ Wt2,
                                        u64 xs0, u64 xs1, u64 xs2,
                                        u64* a0, u64* a1, u64* a2) {
#pragma unroll
    for (int j = 0; j < 32; j++) {
        u64 w = *reinterpret_cast<const u64*>(W1 + 2 * j);
        u64 b = *reinterpret_cast<const u64*>(B1 + 2 * j);
        u64 m0 = f2fma(w, xs0, b);
        u64 m1 = f2fma(w, xs1, b);
        u64 m2 = f2fma(w, xs2, b);
        float e0, f0, e1, f1, e2, f2;
        upk(e0, f0, m0); upk(e1, f1, m1); upk(e2, f2, m2);
        e0 = fmaxf(e0, 0.0f); f0 = fmaxf(f0, 0.0f);
        e1 = fmaxf(e1, 0.0f); f1 = fmaxf(f1, 0.0f);
        e2 = fmaxf(e2, 0.0f); f2 = fmaxf(f2, 0.0f);
        const u64 pa0 = pk2(e0), pb0 = pk2(f0);
        const u64 pa1 = pk2(e1), pb1 = pk2(f1);
        const u64 pa2 = pk2(e2), pb2 = pk2(f2);
        const float* w2a = Wt2 + (2 * j) * 32;
        const float* w2b = w2a + 32;
#pragma unroll
        for (int o = 0; o < 16; o += 2) {
            ulonglong2 wa = *reinterpret_cast<const ulonglong2*>(w2a + 2 * o);
            a0[o]     = f2fma(wa.x, pa0, a0[o]);
            a1[o]     = f2fma(wa.x, pa1, a1[o]);
            a2[o]     = f2fma(wa.x, pa2, a2[o]);
            a0[o + 1] = f2fma(wa.y, pa0, a0[o + 1]);
            a1[o + 1] = f2fma(wa.y, pa1, a1[o + 1]);
            a2[o + 1] = f2fma(wa.y, pa2, a2[o + 1]);
            ulonglong2 wb = *reinterpret_cast<const ulonglong2*>(w2b + 2 * o);
            a0[o]     = f2fma(wb.x, pb0, a0[o]);
            a1[o]     = f2fma(wb.x, pb1, a1[o]);
            a2[o]     = f2fma(wb.x, pb2, a2[o]);
            a0[o + 1] = f2fma(wb.y, pb0, a0[o + 1]);
            a1[o + 1] = f2fma(wb.y, pb1, a1[o + 1]);
            a2[o + 1] = f2fma(wb.y, pb2, a2[o + 1]);
        }
    }
}

__device__ __forceinline__ void cpy(float* dst, const float* __restrict__ src,
                                    int n, int tid) {
    for (int i = tid; i < n; i += NTHREADS) dst[i] = src[i];
}

template<int IN, int OUT>
__device__ __forceinline__ void stage_t(float* dst, const float* __restrict__ src,
                                        int tid) {
    for (int idx = tid; idx < IN * OUT; idx += NTHREADS) {
        int i = idx / OUT;
        int o = idx & (OUT - 1);
        dst[idx] = src[o * IN + i];
    }
}

__global__ void __launch_bounds__(NTHREADS)
mlp32_kernel(const float* __restrict__ x,
             const float* __restrict__ Wa1, const float* __restrict__ ba1,
             const float* __restrict__ Wa2, const float* __restrict__ ba2,
             const float* __restrict__ Wa3, const float* __restrict__ ba3,
             const float* __restrict__ Wa4, const float* __restrict__ ba4,
             const float* __restrict__ Wa5, const float* __restrict__ ba5,
             const float* __restrict__ Wb1, const float* __restrict__ bb1,
             const float* __restrict__ Wb2, const float* __restrict__ bb2,
             const float* __restrict__ Wb3, const float* __restrict__ bb3,
             const float* __restrict__ Wb4, const float* __restrict__ bb4,
             const float* __restrict__ Wb5, const float* __restrict__ bb5,
             const float* __restrict__ Wb6, const float* __restrict__ bb6,
             float* __restrict__ out, int nrows) {
    extern __shared__ float s[];
    float* xs_ = s + OFF_XS;
    const int p = blockIdx.y;
    const int tid = threadIdx.x;

    // ---- stage weights (transposed) ----
    for (int idx = tid; idx < 32 * 64; idx += NTHREADS) {
        int i = idx >> 6, o = idx & 63;
        float v = 0.0f;
        if (i < p)      v = Wb1[(p * 64 + o) * 31 + i];
        else if (i > p) v = Wb1[(p * 64 + o) * 31 + i - 1];
        s[OFF_WB1T + idx] = v;
    }
    stage_t<64, 32>(s + OFF_WB2T, Wb2 + p * 32 * 64, tid);
    stage_t<32, 32>(s + OFF_WB3T, Wb3 + p * 32 * 32, tid);
    stage_t<32, 16>(s + OFF_WB4T, Wb4 + p * 16 * 32, tid);
    stage_t<16, 8>(s + OFF_WB5T, Wb5 + p * 8 * 16, tid);
    stage_t<64, 32>(s + OFF_WA2T, Wa2 + p * 32 * 64, tid);
    stage_t<32, 16>(s + OFF_WA3T, Wa3 + p * 16 * 32, tid);
    stage_t<16, 8>(s + OFF_WA4T, Wa4 + p * 8 * 16, tid);
    cpy(s + OFF_WA1, Wa1 + p * 64, 64, tid);
    cpy(s + OFF_BA1, ba1 + p * 64, 64, tid);
    cpy(s + OFF_BB1, bb1 + p * 64, 64, tid);
    cpy(s + OFF_BB2, bb2 + p * 32, 32, tid);
    cpy(s + OFF_BB3, bb3 + p * 32, 32, tid);
    cpy(s + OFF_BB4, bb4 + p * 16, 16, tid);
    cpy(s + OFF_BA2, ba2 + p * 32, 32, tid);
    cpy(s + OFF_BA3, ba3 + p * 16, 16, tid);
    cpy(s + OFF_BA4, ba4 + p * 8, 8, tid);
    cpy(s + OFF_BB5, bb5 + p * 8, 8, tid);
    cpy(s + OFF_WB6, Wb6 + p * 8, 8, tid);
    cpy(s + OFF_WA5, Wa5 + p * 8, 8, tid);
    if (tid == 0) {
        s[OFF_BB6] = bb6[p];
        s[OFF_BA5] = ba5[p];
    }

    // ---- stage x tile transposed: x_s[i][r] = x[R0+r][i]  (conflict-free, XS%32==1) ----
    const int R0 = blockIdx.x * ROWS_PER_BLOCK;
    const float4* x4 = reinterpret_cast<const float4*>(x);
#pragma unroll
    for (int k = 0; k < (ROWS_PER_BLOCK * 8) / NTHREADS; k++) {
        int idx = tid + k * NTHREADS;
        int r = idx >> 3, i4 = idx & 7;
        float4 v = make_float4(0.f, 0.f, 0.f, 0.f);
        if (R0 + r < nrows) v = x4[(R0 + r) * 8 + i4];
        xs_[(4 * i4 + 0) * XS + r] = v.x;
        xs_[(4 * i4 + 1) * XS + r] = v.y;
        xs_[(4 * i4 + 2) * XS + r] = v.z;
        xs_[(4 * i4 + 3) * XS + r] = v.w;
    }
    __syncthreads();

    const int row0 = R0 + tid;
    const int row1 = row0 + NTHREADS;
    const int row2 = row1 + NTHREADS;
    const float* x0p = xs_ + tid;
    const float* x1p = x0p + NTHREADS;
    const float* x2p = x1p + NTHREADS;

    // ---- encoder B: fused (32->64 relu ->32 raw), then tanh-in packed layers ----
    float bOut0, bOut1, bOut2;
    {
        u64 acc0[16], acc1[16], acc2[16];
#pragma unroll
        for (int o = 0; o < 16; o++) {
            u64 b = *reinterpret_cast<const u64*>(s + OFF_BB2 + 2 * o);
            acc0[o] = b; acc1[o] = b; acc2[o] = b;
        }
        fusedB3<8>(s + OFF_WB1T, s + OFF_BB1, s + OFF_WB2T, x0p, x1p, x2p,
                   acc0, acc1, acc2);
        u64 h3a[16], h3b[16], h3c[16];
        layerP3<32, 32, 2>(s + OFF_WB3T, s + OFF_BB3, acc0, acc1, acc2, h3a, h3b, h3c);
        u64 h4a[8], h4b[8], h4c[8];
        layerP3<32, 16, 2>(s + OFF_WB4T, s + OFF_BB4, h3a, h3b, h3c, h4a, h4b, h4c);
        u64 h5a[4], h5b[4], h5c[4];
        layerP3<16, 8, 2>(s + OFF_WB5T, s + OFF_BB5, h4a, h4b, h4c, h5a, h5b, h5c);
        dotP3<8, 0>(s + OFF_WB6, s[OFF_BB6], h5a, h5b, h5c, bOut0, bOut1, bOut2);
    }

    // ---- encoder A: fused (1->64 relu ->32 raw), ->16, ->8, dot (tanh-in) ----
    float aOut0, aOut1, aOut2;
    {
        u64 acc0[16], acc1[16], acc2[16];
#pragma unroll
        for (int o = 0; o < 16; o++) {
            u64 b = *reinterpret_cast<const u64*>(s + OFF_BA2 + 2 * o);
            acc0[o] = b; acc1[o] = b; acc2[o] = b;
        }
        fusedA3(s + OFF_WA1, s + OFF_BA1, s + OFF_WA2T,
                pk2(x0p[p * XS]), pk2(x1p[p * XS]), pk2(x2p[p * XS]),
                acc0, acc1, acc2);
        u64 a3a[8], a3b[8], a3c[8];
        layerP3<32, 16, 2>(s + OFF_WA3T, s + OFF_BA3, acc0, acc1, acc2, a3a, a3b, a3c);
        u64 a4a[4], a4b[4], a4c[4];
        layerP3<16, 8, 2>(s + OFF_WA4T, s + OFF_BA4, a3a, a3b, a3c, a4a, a4b, a4c);
        dotP3<8, 2>(s + OFF_WA5, s[OFF_BA5], a4a, a4b, a4c, aOut0, aOut1, aOut2);
    }

    if (row0 < nrows) {
        out[row0 * 64 + 2 * p + 0] = aOut0;
        out[row0 * 64 + 2 * p + 1] = bOut0;
    }
    if (row1 < nrows) {
        out[row1 * 64 + 2 * p + 0] = aOut1;
        out[row1 * 64 + 2 * p + 1] = bOut1;
    }
    if (row2 < nrows) {
        out[row2 * 64 + 2 * p + 0] = aOut2;
        out[row2 * 64 + 2 * p + 1] = bOut2;
    }
}

extern "C" void kernel_launch(void* const* d_in, const int* in_sizes, int n_in,
                              void* d_out, int out_size) {
    const float* x   = (const float*)d_in[0];
    const float* Wa1 = (const float*)d_in[1];
    const float* ba1 = (const float*)d_in[2];
    const float* Wa2 = (const float*)d_in[3];
    const float* ba2 = (const float*)d_in[4];
    const float* Wa3 = (const float*)d_in[5];
    const float* ba3 = (const float*)d_in[6];
    const float* Wa4 = (const float*)d_in[7];
    const float* ba4 = (const float*)d_in[8];
    const float* Wa5 = (const float*)d_in[9];
    const float* ba5 = (const float*)d_in[10];
    const float* Wb1 = (const float*)d_in[11];
    const float* bb1 = (const float*)d_in[12];
    const float* Wb2 = (const float*)d_in[13];
    const float* bb2 = (const float*)d_in[14];
    const float* Wb3 = (const float*)d_in[15];
    const float* bb3 = (const float*)d_in[16];
    const float* Wb4 = (const float*)d_in[17];
    const float* bb4 = (const float*)d_in[18];
    const float* Wb5 = (const float*)d_in[19];
    const float* bb5 = (const float*)d_in[20];
    const float* Wb6 = (const float*)d_in[21];
    const float* bb6 = (const float*)d_in[22];
    float* out = (float*)d_out;

    const int nrows = in_sizes[0] / PFEAT;
    const size_t smemBytes = SMEM_FLOATS * sizeof(float);
    cudaFuncSetAttribute(mlp32_kernel,
                         cudaFuncAttributeMaxDynamicSharedMemorySize,
                         (int)smemBytes);
    dim3 grid((nrows + ROWS_PER_BLOCK - 1) / ROWS_PER_BLOCK, PFEAT);
    mlp32_kernel<<<grid, NTHREADS, smemBytes>>>(
        x, Wa1, ba1, Wa2, ba2, Wa3, ba3, Wa4, ba4, Wa5, ba5,
        Wb1, bb1, Wb2, bb2, Wb3, bb3, Wb4, bb4, Wb5, bb5, Wb6, bb6,
        out, nrows);
}

// round 9
// speedup vs baseline: 1.3067x; 1.3067x over previous
#include <cuda_runtime.h>
#include <cuda_bf16.h>
#include <cstdint>

#define NTHREADS 128
#define PFEAT 32
#define CPF 14              // CTAs per feature
#define WARPS 4

// ---- smem float-index offsets ----
// weight planes: per layer [(kb*NB+nb)*64 + lane*2 + b], hi then lo
#define H_B1 0        // KB4 NB8 -> 2048
#define H_B2 2048     // KB8 NB4 -> 2048
#define H_B3 4096     // KB4 NB4 -> 1024
#define H_B4 5120     // KB4 NB2 -> 512
#define H_A2 5632     // KB8 NB4 -> 2048
#define H_A3 7680     // KB4 NB2 -> 512
#define LO_OFS 8192
#define E_BB1 16384
#define E_BB2 16448
#define E_BB3 16480
#define E_BB4 16512
#define E_BA2 16528
#define E_BA3 16560
#define E_WEFF 16576
#define E_BEFF 16592
#define E_WA1 16596
#define E_BA1 16660
#define E_WA4 16724
#define E_BA4 16852
#define E_WA5 16860
#define E_BA5 16868
#define SMEM_FLOATS 16872

__device__ __forceinline__ float fast_tanh(float x) {
    float r; asm("tanh.approx.f32 %0, %1;" : "=f"(r) : "f"(x)); return r;
}
__device__ __forceinline__ void split_tf32(float v, uint32_t& h, uint32_t& l) {
    asm("cvt.rna.tf32.f32 %0, %1;" : "=r"(h) : "f"(v));
    float r = v - __uint_as_float(h);
    asm("cvt.rna.tf32.f32 %0, %1;" : "=r"(l) : "f"(r));
}
__device__ __forceinline__ void mma8(float* d, const uint32_t* a,
                                     uint32_t b0, uint32_t b1) {
    asm volatile(
        "mma.sync.aligned.m16n8k8.row.col.f32.tf32.tf32.f32 "
        "{%0,%1,%2,%3}, {%4,%5,%6,%7}, {%8,%9}, {%0,%1,%2,%3};"
        : "+f"(d[0]), "+f"(d[1]), "+f"(d[2]), "+f"(d[3])
        : "r"(a[0]), "r"(a[1]), "r"(a[2]), "r"(a[3]), "r"(b0), "r"(b1));
}

// tensor layer: D[NB][4] = A(16xKB*8) * W(KB*8 x NB*8), 3-term tf32
template<int KB, int NB>
__device__ __forceinline__ void tlayer(const float* __restrict__ hi,
                                       const float* __restrict__ lo,
                                       const uint32_t (*ah)[4],
                                       const uint32_t (*al)[4],
                                       float (*d)[4], int lane) {
#pragma unroll
    for (int nb = 0; nb < NB; nb++) {
        d[nb][0] = 0.f; d[nb][1] = 0.f; d[nb][2] = 0.f; d[nb][3] = 0.f;
#pragma unroll
        for (int kb = 0; kb < KB; kb++) {
            int base = (kb * NB + nb) * 64 + lane * 2;
            float2 wh = *reinterpret_cast<const float2*>(hi + base);
            float2 wl = *reinterpret_cast<const float2*>(lo + base);
            uint32_t bh0 = __float_as_uint(wh.x), bh1 = __float_as_uint(wh.y);
            uint32_t bl0 = __float_as_uint(wl.x), bl1 = __float_as_uint(wl.y);
            mma8(d[nb], ah[kb], bh0, bh1);
            mma8(d[nb], al[kb], bh0, bh1);
            mma8(d[nb], ah[kb], bl0, bl1);
        }
    }
}

// add bias + activation on D frags. ACT: 1 relu, 2 tanh
template<int NB, int ACT>
__device__ __forceinline__ void biasact(float (*d)[4],
                                        const float* __restrict__ bias, int lane) {
    const int q = lane & 3;
#pragma unroll
    for (int nb = 0; nb < NB; nb++) {
        float b0 = bias[nb * 8 + 2 * q], b1 = bias[nb * 8 + 2 * q + 1];
        float v0 = d[nb][0] + b0, v1 = d[nb][1] + b1;
        float v2 = d[nb][2] + b0, v3 = d[nb][3] + b1;
        if (ACT == 1) { v0 = fmaxf(v0, 0.f); v1 = fmaxf(v1, 0.f);
                        v2 = fmaxf(v2, 0.f); v3 = fmaxf(v3, 0.f); }
        if (ACT == 2) { v0 = fast_tanh(v0); v1 = fast_tanh(v1);
                        v2 = fast_tanh(v2); v3 = fast_tanh(v3); }
        d[nb][0] = v0; d[nb][1] = v1; d[nb][2] = v2; d[nb][3] = v3;
    }
}

// D (m16n8) -> A (m16k8) refragment + tf32 split, per 8-col block
template<int NB>
__device__ __forceinline__ void refrag(const float (*d)[4],
                                       uint32_t (*ah)[4], uint32_t (*al)[4],
                                       int lane) {
    const int q = lane & 3;
    const int s0 = (lane & ~3) | (q >> 1);
    const int s2 = s0 + 2;
    const bool odd = (q & 1) != 0;
#pragma unroll
    for (int j = 0; j < NB; j++) {
        float c0 = d[j][0], c1 = d[j][1], c2 = d[j][2], c3 = d[j][3];
        float t00 = __shfl_sync(0xffffffffu, c0, s0);
        float t10 = __shfl_sync(0xffffffffu, c1, s0);
        float t02 = __shfl_sync(0xffffffffu, c0, s2);
        float t12 = __shfl_sync(0xffffffffu, c1, s2);
        float t20 = __shfl_sync(0xffffffffu, c2, s0);
        float t30 = __shfl_sync(0xffffffffu, c3, s0);
        float t22 = __shfl_sync(0xffffffffu, c2, s2);
        float t32 = __shfl_sync(0xffffffffu, c3, s2);
        float a0 = odd ? t10 : t00;
        float a2 = odd ? t12 : t02;
        float a1 = odd ? t30 : t20;
        float a3 = odd ? t32 : t22;
        split_tf32(a0, ah[j][0], al[j][0]);
        split_tf32(a1, ah[j][1], al[j][1]);
        split_tf32(a2, ah[j][2], al[j][2]);
        split_tf32(a3, ah[j][3], al[j][3]);
    }
}

// stage one layer's weights into hi/lo planes, mma-B layout
template<int IN, int OUT, bool LOO>
__device__ void stageL(float* hi, float* lo, const float* __restrict__ W,
                       int p, int tid) {
    constexpr int KB = IN / 8, NB = OUT / 8;
    for (int idx = tid; idx < KB * NB * 64; idx += NTHREADS) {
        int blk = idx >> 6;
        int r = idx & 63;
        int lane = r >> 1, b = r & 1;
        int kb = blk / NB, nb = blk % NB;
        int n = nb * 8 + (lane >> 2);
        int k = kb * 8 + (lane & 3) + 4 * b;
        float w;
        if (LOO) w = (k == p) ? 0.f : W[n * 31 + (k < p ? k : k - 1)];
        else     w = W[n * IN + k];
        uint32_t h, l;
        split_tf32(w, h, l);
        hi[idx] = __uint_as_float(h);
        lo[idx] = __uint_as_float(l);
    }
}

__device__ __forceinline__ void cpyf(float* dst, const float* __restrict__ src,
                                     int n, int tid) {
    for (int i = tid; i < n; i += NTHREADS) dst[i] = src[i];
}

__global__ void __launch_bounds__(NTHREADS)
mlp32_mma_kernel(const float* __restrict__ x,
                 const float* __restrict__ Wa1, const float* __restrict__ ba1,
                 const float* __restrict__ Wa2, const float* __restrict__ ba2,
                 const float* __restrict__ Wa3, const float* __restrict__ ba3,
                 const float* __restrict__ Wa4, const float* __restrict__ ba4,
                 const float* __restrict__ Wa5, const float* __restrict__ ba5,
                 const float* __restrict__ Wb1, const float* __restrict__ bb1,
                 const float* __restrict__ Wb2, const float* __restrict__ bb2,
                 const float* __restrict__ Wb3, const float* __restrict__ bb3,
                 const float* __restrict__ Wb4, const float* __restrict__ bb4,
                 const float* __restrict__ Wb5, const float* __restrict__ bb5,
                 const float* __restrict__ Wb6, const float* __restrict__ bb6,
                 float* __restrict__ out, int nrows) {
    extern __shared__ float s[];
    const int p = blockIdx.y;
    const int tid = threadIdx.x;
    const int lane = tid & 31;
    const int warp = tid >> 5;
    const int q = lane & 3;

    // ---- stage weights ----
    stageL<32, 64, true >(s + H_B1, s + H_B1 + LO_OFS, Wb1 + p * 64 * 31, p, tid);
    stageL<64, 32, false>(s + H_B2, s + H_B2 + LO_OFS, Wb2 + p * 32 * 64, p, tid);
    stageL<32, 32, false>(s + H_B3, s + H_B3 + LO_OFS, Wb3 + p * 32 * 32, p, tid);
    stageL<32, 16, false>(s + H_B4, s + H_B4 + LO_OFS, Wb4 + p * 16 * 32, p, tid);
    stageL<64, 32, false>(s + H_A2, s + H_A2 + LO_OFS, Wa2 + p * 32 * 64, p, tid);
    stageL<32, 16, false>(s + H_A3, s + H_A3 + LO_OFS, Wa3 + p * 16 * 32, p, tid);
    cpyf(s + E_BB1, bb1 + p * 64, 64, tid);
    cpyf(s + E_BB2, bb2 + p * 32, 32, tid);
    cpyf(s + E_BB3, bb3 + p * 32, 32, tid);
    cpyf(s + E_BB4, bb4 + p * 16, 16, tid);
    cpyf(s + E_BA2, ba2 + p * 32, 32, tid);
    cpyf(s + E_BA3, ba3 + p * 16, 16, tid);
    cpyf(s + E_WA1, Wa1 + p * 64, 64, tid);
    cpyf(s + E_BA1, ba1 + p * 64, 64, tid);
    cpyf(s + E_WA4, Wa4 + p * 128, 128, tid);
    cpyf(s + E_BA4, ba4 + p * 8, 8, tid);
    cpyf(s + E_WA5, Wa5 + p * 8, 8, tid);
    // collapsed B5∘B6: w_eff[i] = sum_o Wb6[o]*Wb5[o][i]; b_eff = Wb6·bb5 + bb6
    if (tid < 16) {
        float acc = 0.f;
        for (int o = 0; o < 8; o++)
            acc = fmaf(Wb6[p * 8 + o], Wb5[p * 128 + o * 16 + tid], acc);
        s[E_WEFF + tid] = acc;
    }
    if (tid == 0) {
        float acc = bb6[p];
        for (int o = 0; o < 8; o++)
            acc = fmaf(Wb6[p * 8 + o], bb5[p * 8 + o], acc);
        s[E_BEFF] = acc;
        s[E_BA5] = ba5[p];
    }
    __syncthreads();

    const int NT = nrows >> 4;   // 16-row warp-tiles (nrows % 16 == 0)
    uint32_t ah[8][4], al[8][4];
    float d[8][4];

    for (int t = blockIdx.x * WARPS + warp; t < NT; t += CPF * WARPS) {
        const int rg = t * 16 + (lane >> 2);   // rows rg and rg+8

        // ======== encoder B ========
        // A-frags of padded x (col p is zeroed in LB1 weights)
#pragma unroll
        for (int kb = 0; kb < 4; kb++) {
            float a0 = x[rg * 32 + kb * 8 + q];
            float a1 = x[(rg + 8) * 32 + kb * 8 + q];
            float a2 = x[rg * 32 + kb * 8 + q + 4];
            float a3 = x[(rg + 8) * 32 + kb * 8 + q + 4];
            split_tf32(a0, ah[kb][0], al[kb][0]);
            split_tf32(a1, ah[kb][1], al[kb][1]);
            split_tf32(a2, ah[kb][2], al[kb][2]);
            split_tf32(a3, ah[kb][3], al[kb][3]);
        }
        tlayer<4, 8>(s + H_B1, s + H_B1 + LO_OFS, ah, al, d, lane);
        biasact<8, 1>(d, s + E_BB1, lane);
        refrag<8>(d, ah, al, lane);
        tlayer<8, 4>(s + H_B2, s + H_B2 + LO_OFS, ah, al, d, lane);
        biasact<4, 2>(d, s + E_BB2, lane);
        refrag<4>(d, ah, al, lane);
        tlayer<4, 4>(s + H_B3, s + H_B3 + LO_OFS, ah, al, d, lane);
        biasact<4, 2>(d, s + E_BB3, lane);
        refrag<4>(d, ah, al, lane);
        tlayer<4, 2>(s + H_B4, s + H_B4 + LO_OFS, ah, al, d, lane);
        biasact<2, 2>(d, s + E_BB4, lane);
        // collapsed 16->1 dot
        float pg = 0.f, pg8 = 0.f;
#pragma unroll
        for (int nb = 0; nb < 2; nb++) {
            float w0 = s[E_WEFF + nb * 8 + 2 * q];
            float w1 = s[E_WEFF + nb * 8 + 2 * q + 1];
            pg  = fmaf(d[nb][0], w0, fmaf(d[nb][1], w1, pg));
            pg8 = fmaf(d[nb][2], w0, fmaf(d[nb][3], w1, pg8));
        }
        pg  += __shfl_xor_sync(0xffffffffu, pg, 1);
        pg  += __shfl_xor_sync(0xffffffffu, pg, 2);
        pg8 += __shfl_xor_sync(0xffffffffu, pg8, 1);
        pg8 += __shfl_xor_sync(0xffffffffu, pg8, 2);
        const float bOut_g  = pg + s[E_BEFF];
        const float bOut_g8 = pg8 + s[E_BEFF];

        // ======== encoder A ========
        const float xs_g  = x[rg * 32 + p];
        const float xs_g8 = x[(rg + 8) * 32 + p];
#pragma unroll
        for (int kb = 0; kb < 8; kb++) {
            int c0 = kb * 8 + q, c1 = c0 + 4;
            float a0 = fmaxf(fmaf(s[E_WA1 + c0], xs_g,  s[E_BA1 + c0]), 0.f);
            float a1 = fmaxf(fmaf(s[E_WA1 + c0], xs_g8, s[E_BA1 + c0]), 0.f);
            float a2 = fmaxf(fmaf(s[E_WA1 + c1], xs_g,  s[E_BA1 + c1]), 0.f);
            float a3 = fmaxf(fmaf(s[E_WA1 + c1], xs_g8, s[E_BA1 + c1]), 0.f);
            split_tf32(a0, ah[kb][0], al[kb][0]);
            split_tf32(a1, ah[kb][1], al[kb][1]);
            split_tf32(a2, ah[kb][2], al[kb][2]);
            split_tf32(a3, ah[kb][3], al[kb][3]);
        }
        tlayer<8, 4>(s + H_A2, s + H_A2 + LO_OFS, ah, al, d, lane);
        biasact<4, 2>(d, s + E_BA2, lane);
        refrag<4>(d, ah, al, lane);
        tlayer<4, 2>(s + H_A3, s + H_A3 + LO_OFS, ah, al, d, lane);
        biasact<2, 2>(d, s + E_BA3, lane);
        // A4 (16->8, tanh) + A5 (8->1) via quad reduction
        float accg = s[E_BA5], accg8 = s[E_BA5];
#pragma unroll
        for (int o = 0; o < 8; o++) {
            float sg = 0.f, sg8 = 0.f;
#pragma unroll
            for (int nb = 0; nb < 2; nb++) {
                int c0 = nb * 8 + 2 * q, c1 = c0 + 1;
                float w0 = s[E_WA4 + o * 16 + c0];
                float w1 = s[E_WA4 + o * 16 + c1];
                sg  = fmaf(d[nb][0], w0, fmaf(d[nb][1], w1, sg));
                sg8 = fmaf(d[nb][2], w0, fmaf(d[nb][3], w1, sg8));
            }
            sg  += __shfl_xor_sync(0xffffffffu, sg, 1);
            sg  += __shfl_xor_sync(0xffffffffu, sg, 2);
            sg8 += __shfl_xor_sync(0xffffffffu, sg8, 1);
            sg8 += __shfl_xor_sync(0xffffffffu, sg8, 2);
            const float w5 = s[E_WA5 + o], b4 = s[E_BA4 + o];
            accg  = fmaf(w5, fast_tanh(sg + b4), accg);
            accg8 = fmaf(w5, fast_tanh(sg8 + b4), accg8);
        }

        if (q == 0) {
            out[rg * 64 + 2 * p + 0] = accg;
            out[rg * 64 + 2 * p + 1] = bOut_g;
            out[(rg + 8) * 64 + 2 * p + 0] = accg8;
            out[(rg + 8) * 64 + 2 * p + 1] = bOut_g8;
        }
    }
}

extern "C" void kernel_launch(void* const* d_in, const int* in_sizes, int n_in,
                              void* d_out, int out_size) {
    const float* x   = (const float*)d_in[0];
    const float* Wa1 = (const float*)d_in[1];
    const float* ba1 = (const float*)d_in[2];
    const float* Wa2 = (const float*)d_in[3];
    const float* ba2 = (const float*)d_in[4];
    const float* Wa3 = (const float*)d_in[5];
    const float* ba3 = (const float*)d_in[6];
    const float* Wa4 = (const float*)d_in[7];
    const float* ba4 = (const float*)d_in[8];
    const float* Wa5 = (const float*)d_in[9];
    const float* ba5 = (const float*)d_in[10];
    const float* Wb1 = (const float*)d_in[11];
    const float* bb1 = (const float*)d_in[12];
    const float* Wb2 = (const float*)d_in[13];
    const float* bb2 = (const float*)d_in[14];
    const float* Wb3 = (const float*)d_in[15];
    const float* bb3 = (const float*)d_in[16];
    const float* Wb4 = (const float*)d_in[17];
    const float* bb4 = (const float*)d_in[18];
    const float* Wb5 = (const float*)d_in[19];
    const float* bb5 = (const float*)d_in[20];
    const float* Wb6 = (const float*)d_in[21];
    const float* bb6 = (const float*)d_in[22];
    float* out = (float*)d_out;

    const int nrows = in_sizes[0] / PFEAT;
    const size_t smemBytes = SMEM_FLOATS * sizeof(float);
    cudaFuncSetAttribute(mlp32_mma_kernel,
                         cudaFuncAttributeMaxDynamicSharedMemorySize,
                         (int)smemBytes);
    dim3 grid(CPF, PFEAT);
    mlp32_mma_kernel<<<grid, NTHREADS, smemBytes>>>(
        x, Wa1, ba1, Wa2, ba2, Wa3, ba3, Wa4, ba4, Wa5, ba5,
        Wb1, bb1, Wb2, bb2, Wb3, bb3, Wb4, bb4, Wb5, bb5, Wb6, bb6,
        out, nrows);
}

// round 10
// speedup vs baseline: 1.7971x; 1.3753x over previous
#include <cuda_runtime.h>
#include <cuda_bf16.h>
#include <cstdint>

#define NTHREADS 256
#define WARPS 8
#define PFEAT 32
#define CPF 13              // CTAs per feature -> 416 CTAs total (single wave)

// ---- smem float-index offsets ----
// weight planes: per (kb,nb) block, per lane: float4 {wh0, wh1, wl0, wl1}
// at (blk*32 + lane)*4.  Layer sizes: KB*NB*128 floats.
#define W_B1 0        // KB4 NB8 -> 4096
#define W_B2 4096     // KB8 NB4 -> 4096
#define W_B3 8192     // KB4 NB4 -> 2048
#define W_B4 10240    // KB4 NB2 -> 1024
#define W_A2 11264    // KB8 NB4 -> 4096
#define W_A3 15360    // KB4 NB2 -> 1024
#define E_BB1 16384
#define E_BB2 16448
#define E_BB3 16480
#define E_BB4 16512
#define E_BA2 16528
#define E_BA3 16560
#define E_WEFF 16576
#define E_BEFF 16592
#define E_WA1 16596
#define E_BA1 16660
#define E_WA4 16724
#define E_BA4 16852
#define E_WA5 16860
#define E_BA5 16868
#define SMEM_FLOATS 16872

__device__ __forceinline__ float fast_tanh(float x) {
    float r; asm("tanh.approx.f32 %0, %1;" : "=f"(r) : "f"(x)); return r;
}
__device__ __forceinline__ void split_tf32(float v, uint32_t& h, uint32_t& l) {
    asm("cvt.rna.tf32.f32 %0, %1;" : "=r"(h) : "f"(v));
    float r = v - __uint_as_float(h);
    asm("cvt.rna.tf32.f32 %0, %1;" : "=r"(l) : "f"(r));
}
__device__ __forceinline__ void mma8(float* d, const uint32_t* a,
                                     uint32_t b0, uint32_t b1) {
    asm volatile(
        "mma.sync.aligned.m16n8k8.row.col.f32.tf32.tf32.f32 "
        "{%0,%1,%2,%3}, {%4,%5,%6,%7}, {%8,%9}, {%0,%1,%2,%3};"
        : "+f"(d[0]), "+f"(d[1]), "+f"(d[2]), "+f"(d[3])
        : "r"(a[0]), "r"(a[1]), "r"(a[2]), "r"(a[3]), "r"(b0), "r"(b1));
}

// tensor layer: D[NB][4] = A(16xKB*8) * W(KB*8 x NB*8), 3-term tf32,
// weights fetched as one float4 {wh0,wh1,wl0,wl1} per lane per block
template<int KB, int NB>
__device__ __forceinline__ void tlayer(const float* __restrict__ wp,
                                       const uint32_t (*ah)[4],
                                       const uint32_t (*al)[4],
                                       float (*d)[4], int lane) {
#pragma unroll
    for (int nb = 0; nb < NB; nb++) {
        d[nb][0] = 0.f; d[nb][1] = 0.f; d[nb][2] = 0.f; d[nb][3] = 0.f;
#pragma unroll
        for (int kb = 0; kb < KB; kb++) {
            float4 w = *reinterpret_cast<const float4*>(
                wp + ((kb * NB + nb) * 32 + lane) * 4);
            uint32_t bh0 = __float_as_uint(w.x), bh1 = __float_as_uint(w.y);
            uint32_t bl0 = __float_as_uint(w.z), bl1 = __float_as_uint(w.w);
            mma8(d[nb], ah[kb], bh0, bh1);
            mma8(d[nb], al[kb], bh0, bh1);
            mma8(d[nb], ah[kb], bl0, bl1);
        }
    }
}

// add bias + activation on D frags. ACT: 1 relu, 2 tanh
template<int NB, int ACT>
__device__ __forceinline__ void biasact(float (*d)[4],
                                        const float* __restrict__ bias, int lane) {
    const int q = lane & 3;
#pragma unroll
    for (int nb = 0; nb < NB; nb++) {
        float b0 = bias[nb * 8 + 2 * q], b1 = bias[nb * 8 + 2 * q + 1];
        float v0 = d[nb][0] + b0, v1 = d[nb][1] + b1;
        float v2 = d[nb][2] + b0, v3 = d[nb][3] + b1;
        if (ACT == 1) { v0 = fmaxf(v0, 0.f); v1 = fmaxf(v1, 0.f);
                        v2 = fmaxf(v2, 0.f); v3 = fmaxf(v3, 0.f); }
        if (ACT == 2) { v0 = fast_tanh(v0); v1 = fast_tanh(v1);
                        v2 = fast_tanh(v2); v3 = fast_tanh(v3); }
        d[nb][0] = v0; d[nb][1] = v1; d[nb][2] = v2; d[nb][3] = v3;
    }
}

// D (m16n8) -> A (m16k8) refragment + tf32 split, per 8-col block
template<int NB>
__device__ __forceinline__ void refrag(const float (*d)[4],
                                       uint32_t (*ah)[4], uint32_t (*al)[4],
                                       int lane) {
    const int q = lane & 3;
    const int s0 = (lane & ~3) | (q >> 1);
    const int s2 = s0 + 2;
    const bool odd = (q & 1) != 0;
#pragma unroll
    for (int j = 0; j < NB; j++) {
        float c0 = d[j][0], c1 = d[j][1], c2 = d[j][2], c3 = d[j][3];
        float t00 = __shfl_sync(0xffffffffu, c0, s0);
        float t10 = __shfl_sync(0xffffffffu, c1, s0);
        float t02 = __shfl_sync(0xffffffffu, c0, s2);
        float t12 = __shfl_sync(0xffffffffu, c1, s2);
        float t20 = __shfl_sync(0xffffffffu, c2, s0);
        float t30 = __shfl_sync(0xffffffffu, c3, s0);
        float t22 = __shfl_sync(0xffffffffu, c2, s2);
        float t32 = __shfl_sync(0xffffffffu, c3, s2);
        float a0 = odd ? t10 : t00;
        float a2 = odd ? t12 : t02;
        float a1 = odd ? t30 : t20;
        float a3 = odd ? t32 : t22;
        split_tf32(a0, ah[j][0], al[j][0]);
        split_tf32(a1, ah[j][1], al[j][1]);
        split_tf32(a2, ah[j][2], al[j][2]);
        split_tf32(a3, ah[j][3], al[j][3]);
    }
}

// stage one layer's weights, interleaved hi/lo float4 layout
template<int IN, int OUT, bool LOO>
__device__ void stageL(float* wp, const float* __restrict__ W, int p, int tid) {
    constexpr int KB = IN / 8, NB = OUT / 8;
    for (int idx = tid; idx < KB * NB * 64; idx += NTHREADS) {
        int blk = idx >> 6;
        int r = idx & 63;
        int lane = r >> 1, b = r & 1;
        int kb = blk / NB, nb = blk % NB;
        int n = nb * 8 + (lane >> 2);
        int k = kb * 8 + (lane & 3) + 4 * b;
        float w;
        if (LOO) w = (k == p) ? 0.f : W[n * 31 + (k < p ? k : k - 1)];
        else     w = W[n * IN + k];
        uint32_t h, l;
        split_tf32(w, h, l);
        wp[blk * 128 + lane * 4 + b] = __uint_as_float(h);
        wp[blk * 128 + lane * 4 + 2 + b] = __uint_as_float(l);
    }
}

__device__ __forceinline__ void cpyf(float* dst, const float* __restrict__ src,
                                     int n, int tid) {
    for (int i = tid; i < n; i += NTHREADS) dst[i] = src[i];
}

__global__ void __launch_bounds__(NTHREADS)
mlp32_mma_kernel(const float* __restrict__ x,
                 const float* __restrict__ Wa1, const float* __restrict__ ba1,
                 const float* __restrict__ Wa2, const float* __restrict__ ba2,
                 const float* __restrict__ Wa3, const float* __restrict__ ba3,
                 const float* __restrict__ Wa4, const float* __restrict__ ba4,
                 const float* __restrict__ Wa5, const float* __restrict__ ba5,
                 const float* __restrict__ Wb1, const float* __restrict__ bb1,
                 const float* __restrict__ Wb2, const float* __restrict__ bb2,
                 const float* __restrict__ Wb3, const float* __restrict__ bb3,
                 const float* __restrict__ Wb4, const float* __restrict__ bb4,
                 const float* __restrict__ Wb5, const float* __restrict__ bb5,
                 const float* __restrict__ Wb6, const float* __restrict__ bb6,
                 float* __restrict__ out, int nrows) {
    extern __shared__ float s[];
    const int p = blockIdx.y;
    const int tid = threadIdx.x;
    const int lane = tid & 31;
    const int warp = tid >> 5;
    const int q = lane & 3;

    // ---- stage weights ----
    stageL<32, 64, true >(s + W_B1, Wb1 + p * 64 * 31, p, tid);
    stageL<64, 32, false>(s + W_B2, Wb2 + p * 32 * 64, p, tid);
    stageL<32, 32, false>(s + W_B3, Wb3 + p * 32 * 32, p, tid);
    stageL<32, 16, false>(s + W_B4, Wb4 + p * 16 * 32, p, tid);
    stageL<64, 32, false>(s + W_A2, Wa2 + p * 32 * 64, p, tid);
    stageL<32, 16, false>(s + W_A3, Wa3 + p * 16 * 32, p, tid);
    cpyf(s + E_BB1, bb1 + p * 64, 64, tid);
    cpyf(s + E_BB2, bb2 + p * 32, 32, tid);
    cpyf(s + E_BB3, bb3 + p * 32, 32, tid);
    cpyf(s + E_BB4, bb4 + p * 16, 16, tid);
    cpyf(s + E_BA2, ba2 + p * 32, 32, tid);
    cpyf(s + E_BA3, ba3 + p * 16, 16, tid);
    cpyf(s + E_WA1, Wa1 + p * 64, 64, tid);
    cpyf(s + E_BA1, ba1 + p * 64, 64, tid);
    cpyf(s + E_WA4, Wa4 + p * 128, 128, tid);
    cpyf(s + E_BA4, ba4 + p * 8, 8, tid);
    cpyf(s + E_WA5, Wa5 + p * 8, 8, tid);
    // collapsed B5∘B6 (both linear): w_eff[i] = sum_o Wb6[o]*Wb5[o][i]
    if (tid < 16) {
        float acc = 0.f;
        for (int o = 0; o < 8; o++)
            acc = fmaf(Wb6[p * 8 + o], Wb5[p * 128 + o * 16 + tid], acc);
        s[E_WEFF + tid] = acc;
    }
    if (tid == 0) {
        float acc = bb6[p];
        for (int o = 0; o < 8; o++)
            acc = fmaf(Wb6[p * 8 + o], bb5[p * 8 + o], acc);
        s[E_BEFF] = acc;
        s[E_BA5] = ba5[p];
    }
    __syncthreads();

    const int NT = nrows >> 4;   // 16-row warp-tiles
    uint32_t ah[8][4], al[8][4];
    float d[8][4];

    for (int t = blockIdx.x * WARPS + warp; t < NT; t += CPF * WARPS) {
        const int rg = t * 16 + (lane >> 2);   // rows rg and rg+8

        // ======== encoder B ========
#pragma unroll
        for (int kb = 0; kb < 4; kb++) {
            float a0 = x[rg * 32 + kb * 8 + q];
            float a1 = x[(rg + 8) * 32 + kb * 8 + q];
            float a2 = x[rg * 32 + kb * 8 + q + 4];
            float a3 = x[(rg + 8) * 32 + kb * 8 + q + 4];
            split_tf32(a0, ah[kb][0], al[kb][0]);
            split_tf32(a1, ah[kb][1], al[kb][1]);
            split_tf32(a2, ah[kb][2], al[kb][2]);
            split_tf32(a3, ah[kb][3], al[kb][3]);
        }
        tlayer<4, 8>(s + W_B1, ah, al, d, lane);
        biasact<8, 1>(d, s + E_BB1, lane);
        refrag<8>(d, ah, al, lane);
        tlayer<8, 4>(s + W_B2, ah, al, d, lane);
        biasact<4, 2>(d, s + E_BB2, lane);
        refrag<4>(d, ah, al, lane);
        tlayer<4, 4>(s + W_B3, ah, al, d, lane);
        biasact<4, 2>(d, s + E_BB3, lane);
        refrag<4>(d, ah, al, lane);
        tlayer<4, 2>(s + W_B4, ah, al, d, lane);
        biasact<2, 2>(d, s + E_BB4, lane);
        // collapsed 16->1 dot
        float pg = 0.f, pg8 = 0.f;
#pragma unroll
        for (int nb = 0; nb < 2; nb++) {
            float w0 = s[E_WEFF + nb * 8 + 2 * q];
            float w1 = s[E_WEFF + nb * 8 + 2 * q + 1];
            pg  = fmaf(d[nb][0], w0, fmaf(d[nb][1], w1, pg));
            pg8 = fmaf(d[nb][2], w0, fmaf(d[nb][3], w1, pg8));
        }
        pg  += __shfl_xor_sync(0xffffffffu, pg, 1);
        pg  += __shfl_xor_sync(0xffffffffu, pg, 2);
        pg8 += __shfl_xor_sync(0xffffffffu, pg8, 1);
        pg8 += __shfl_xor_sync(0xffffffffu, pg8, 2);
        const float bOut_g  = pg + s[E_BEFF];
        const float bOut_g8 = pg8 + s[E_BEFF];

        // ======== encoder A ========
        const float xs_g  = x[rg * 32 + p];
        const float xs_g8 = x[(rg + 8) * 32 + p];
#pragma unroll
        for (int kb = 0; kb < 8; kb++) {
            int c0 = kb * 8 + q, c1 = c0 + 4;
            float a0 = fmaxf(fmaf(s[E_WA1 + c0], xs_g,  s[E_BA1 + c0]), 0.f);
            float a1 = fmaxf(fmaf(s[E_WA1 + c0], xs_g8, s[E_BA1 + c0]), 0.f);
            float a2 = fmaxf(fmaf(s[E_WA1 + c1], xs_g,  s[E_BA1 + c1]), 0.f);
            float a3 = fmaxf(fmaf(s[E_WA1 + c1], xs_g8, s[E_BA1 + c1]), 0.f);
            split_tf32(a0, ah[kb][0], al[kb][0]);
            split_tf32(a1, ah[kb][1], al[kb][1]);
            split_tf32(a2, ah[kb][2], al[kb][2]);
            split_tf32(a3, ah[kb][3], al[kb][3]);
        }
        tlayer<8, 4>(s + W_A2, ah, al, d, lane);
        biasact<4, 2>(d, s + E_BA2, lane);
        refrag<4>(d, ah, al, lane);
        tlayer<4, 2>(s + W_A3, ah, al, d, lane);
        biasact<2, 2>(d, s + E_BA3, lane);
        // A4 (16->8, tanh) + A5 (8->1) via quad reduction
        float accg = s[E_BA5], accg8 = s[E_BA5];
#pragma unroll
        for (int o = 0; o < 8; o++) {
            float sg = 0.f, sg8 = 0.f;
#pragma unroll
            for (int nb = 0; nb < 2; nb++) {
                int c0 = nb * 8 + 2 * q, c1 = c0 + 1;
                float w0 = s[E_WA4 + o * 16 + c0];
                float w1 = s[E_WA4 + o * 16 + c1];
                sg  = fmaf(d[nb][0], w0, fmaf(d[nb][1], w1, sg));
                sg8 = fmaf(d[nb][2], w0, fmaf(d[nb][3], w1, sg8));
            }
            sg  += __shfl_xor_sync(0xffffffffu, sg, 1);
            sg  += __shfl_xor_sync(0xffffffffu, sg, 2);
            sg8 += __shfl_xor_sync(0xffffffffu, sg8, 1);
            sg8 += __shfl_xor_sync(0xffffffffu, sg8, 2);
            const float w5 = s[E_WA5 + o], b4 = s[E_BA4 + o];
            accg  = fmaf(w5, fast_tanh(sg + b4), accg);
            accg8 = fmaf(w5, fast_tanh(sg8 + b4), accg8);
        }

        if (q == 0) {
            out[rg * 64 + 2 * p + 0] = accg;
            out[rg * 64 + 2 * p + 1] = bOut_g;
            out[(rg + 8) * 64 + 2 * p + 0] = accg8;
            out[(rg + 8) * 64 + 2 * p + 1] = bOut_g8;
        }
    }
}

extern "C" void kernel_launch(void* const* d_in, const int* in_sizes, int n_in,
                              void* d_out, int out_size) {
    const float* x   = (const float*)d_in[0];
    const float* Wa1 = (const float*)d_in[1];
    const float* ba1 = (const float*)d_in[2];
    const float* Wa2 = (const float*)d_in[3];
    const float* ba2 = (const float*)d_in[4];
    const float* Wa3 = (const float*)d_in[5];
    const float* ba3 = (const float*)d_in[6];
    const float* Wa4 = (const float*)d_in[7];
    const float* ba4 = (const float*)d_in[8];
    const float* Wa5 = (const float*)d_in[9];
    const float* ba5 = (const float*)d_in[10];
    const float* Wb1 = (const float*)d_in[11];
    const float* bb1 = (const float*)d_in[12];
    const float* Wb2 = (const float*)d_in[13];
    const float* bb2 = (const float*)d_in[14];
    const float* Wb3 = (const float*)d_in[15];
    const float* bb3 = (const float*)d_in[16];
    const float* Wb4 = (const float*)d_in[17];
    const float* bb4 = (const float*)d_in[18];
    const float* Wb5 = (const float*)d_in[19];
    const float* bb5 = (const float*)d_in[20];
    const float* Wb6 = (const float*)d_in[21];
    const float* bb6 = (const float*)d_in[22];
    float* out = (float*)d_out;

    const int nrows = in_sizes[0] / PFEAT;
    const size_t smemBytes = SMEM_FLOATS * sizeof(float);
    cudaFuncSetAttribute(mlp32_mma_kernel,
                         cudaFuncAttributeMaxDynamicSharedMemorySize,
                         (int)smemBytes);
    dim3 grid(CPF, PFEAT);
    mlp32_mma_kernel<<<grid, NTHREADS, smemBytes>>>(
        x, Wa1, ba1, Wa2, ba2, Wa3, ba3, Wa4, ba4, Wa5, ba5,
        Wb1, bb1, Wb2, bb2, Wb3, bb3, Wb4, bb4, Wb5, bb5, Wb6, bb6,
        out, nrows);
}

// round 11
// speedup vs baseline: 1.9605x; 1.0909x over previous
#include <cuda_runtime.h>
#include <cuda_bf16.h>
#include <cstdint>

#define NTHREADS 256
#define WARPS 8
#define PFEAT 32
#define CPF 13              // 416 CTAs total (single wave at 3 CTA/SM)

// ---- smem float-index offsets ----
// weight planes: per (kb,nb) block, per lane: float4 {wh0, wh1, wl0, wl1}
#define W_B1 0        // KB4 NB8 -> 4096
#define W_B2 4096     // KB8 NB4 -> 4096
#define W_B3 8192     // KB4 NB4 -> 2048
#define W_B4 10240    // KB4 NB2 -> 1024
#define W_A2 11264    // KB8 NB4 -> 4096
#define W_A3 15360    // KB4 NB2 -> 1024
#define E_BB1 16384
#define E_BB2 16448
#define E_BB3 16480
#define E_BB4 16512
#define E_BA2 16528
#define E_BA3 16560
#define E_WEFF 16576
#define E_BEFF 16592
#define E_WA1 16596
#define E_BA1 16660
#define E_WA4 16724
#define E_BA4 16852
#define E_WA5 16860
#define E_BA5 16868
#define SMEM_FLOATS 16872

__device__ __forceinline__ float fast_tanh(float x) {
    float r; asm("tanh.approx.f32 %0, %1;" : "=f"(r) : "f"(x)); return r;
}
// tf32 split via truncation: hi = v masked to tf32 bits (exact tf32),
// lo = v - hi (exact fp32). Raw bits passed to mma (HW ignores low 13 bits).
__device__ __forceinline__ void split2(float v, uint32_t& h, uint32_t& l) {
    uint32_t hv = __float_as_uint(v) & 0xffffe000u;
    h = hv;
    l = __float_as_uint(v - __uint_as_float(hv));
}
__device__ __forceinline__ void mma8(float* d, const uint32_t* a,
                                     uint32_t b0, uint32_t b1) {
    asm volatile(
        "mma.sync.aligned.m16n8k8.row.col.f32.tf32.tf32.f32 "
        "{%0,%1,%2,%3}, {%4,%5,%6,%7}, {%8,%9}, {%0,%1,%2,%3};"
        : "+f"(d[0]), "+f"(d[1]), "+f"(d[2]), "+f"(d[3])
        : "r"(a[0]), "r"(a[1]), "r"(a[2]), "r"(a[3]), "r"(b0), "r"(b1));
}

// bias + activation on D frags. ACT: 1 relu, 2 tanh
template<int NB, int ACT>
__device__ __forceinline__ void biasact(float (*d)[4],
                                        const float* __restrict__ bias, int lane) {
    const int q = lane & 3;
#pragma unroll
    for (int nb = 0; nb < NB; nb++) {
        float b0 = bias[nb * 8 + 2 * q], b1 = bias[nb * 8 + 2 * q + 1];
        float v0 = d[nb][0] + b0, v1 = d[nb][1] + b1;
        float v2 = d[nb][2] + b0, v3 = d[nb][3] + b1;
        if (ACT == 1) { v0 = fmaxf(v0, 0.f); v1 = fmaxf(v1, 0.f);
                        v2 = fmaxf(v2, 0.f); v3 = fmaxf(v3, 0.f); }
        if (ACT == 2) { v0 = fast_tanh(v0); v1 = fast_tanh(v1);
                        v2 = fast_tanh(v2); v3 = fast_tanh(v3); }
        d[nb][0] = v0; d[nb][1] = v1; d[nb][2] = v2; d[nb][3] = v3;
    }
}

// one D block (m16n8) -> one A block (m16k8) + split
__device__ __forceinline__ void refrag1(const float* dj, uint32_t* ah,
                                        uint32_t* al, int lane) {
    const int q = lane & 3;
    const int s0 = (lane & ~3) | (q >> 1);
    const int s2 = s0 + 2;
    const bool odd = (q & 1) != 0;
    float c0 = dj[0], c1 = dj[1], c2 = dj[2], c3 = dj[3];
    float t00 = __shfl_sync(0xffffffffu, c0, s0);
    float t10 = __shfl_sync(0xffffffffu, c1, s0);
    float t02 = __shfl_sync(0xffffffffu, c0, s2);
    float t12 = __shfl_sync(0xffffffffu, c1, s2);
    float t20 = __shfl_sync(0xffffffffu, c2, s0);
    float t30 = __shfl_sync(0xffffffffu, c3, s0);
    float t22 = __shfl_sync(0xffffffffu, c2, s2);
    float t32 = __shfl_sync(0xffffffffu, c3, s2);
    float a0 = odd ? t10 : t00;
    float a2 = odd ? t12 : t02;
    float a1 = odd ? t30 : t20;
    float a3 = odd ? t32 : t22;
    split2(a0, ah[0], al[0]);
    split2(a1, ah[1], al[1]);
    split2(a2, ah[2], al[2]);
    split2(a3, ah[3], al[3]);
}

// streamed layer: consume previous D blocks one at a time
template<int KB, int NB>
__device__ __forceinline__ void layer_stream(const float* __restrict__ wp,
                                             const float (*dp)[4],
                                             float (*dn)[4], int lane) {
#pragma unroll
    for (int nb = 0; nb < NB; nb++) {
        dn[nb][0] = 0.f; dn[nb][1] = 0.f; dn[nb][2] = 0.f; dn[nb][3] = 0.f;
    }
#pragma unroll
    for (int j = 0; j < KB; j++) {
        uint32_t ah[4], al[4];
        refrag1(dp[j], ah, al, lane);
#pragma unroll
        for (int nb = 0; nb < NB; nb++) {
            float4 w = *reinterpret_cast<const float4*>(
                wp + ((j * NB + nb) * 32 + lane) * 4);
            uint32_t bh0 = __float_as_uint(w.x), bh1 = __float_as_uint(w.y);
            uint32_t bl0 = __float_as_uint(w.z), bl1 = __float_as_uint(w.w);
            mma8(dn[nb], ah, bh0, bh1);
            mma8(dn[nb], al, bh0, bh1);
            mma8(dn[nb], ah, bl0, bl1);
        }
    }
}

// stage one layer's weights, interleaved hi/lo float4 layout
template<int IN, int OUT, bool LOO>
__device__ void stageL(float* wp, const float* __restrict__ W, int p, int tid) {
    constexpr int NB = OUT / 8;
    constexpr int KB = IN / 8;
    for (int idx = tid; idx < KB * NB * 64; idx += NTHREADS) {
        int blk = idx >> 6;
        int r = idx & 63;
        int lane = r >> 1, b = r & 1;
        int nb = blk % NB;
        int kb = blk / NB;
        int n = nb * 8 + (lane >> 2);
        int k = kb * 8 + (lane & 3) + 4 * b;
        float w;
        if (LOO) w = (k == p) ? 0.f : W[n * 31 + (k < p ? k : k - 1)];
        else     w = W[n * IN + k];
        uint32_t h, l;
        split2(w, h, l);
        // clean lo to tf32 truncation as well (HW would anyway)
        wp[blk * 128 + lane * 4 + b] = __uint_as_float(h);
        wp[blk * 128 + lane * 4 + 2 + b] = __uint_as_float(l);
    }
}

__device__ __forceinline__ void cpyf(float* dst, const float* __restrict__ src,
                                     int n, int tid) {
    for (int i = tid; i < n; i += NTHREADS) dst[i] = src[i];
}

__global__ void __launch_bounds__(NTHREADS, 3)
mlp32_mma_kernel(const float* __restrict__ x,
                 const float* __restrict__ Wa1, const float* __restrict__ ba1,
                 const float* __restrict__ Wa2, const float* __restrict__ ba2,
                 const float* __restrict__ Wa3, const float* __restrict__ ba3,
                 const float* __restrict__ Wa4, const float* __restrict__ ba4,
                 const float* __restrict__ Wa5, const float* __restrict__ ba5,
                 const float* __restrict__ Wb1, const float* __restrict__ bb1,
                 const float* __restrict__ Wb2, const float* __restrict__ bb2,
                 const float* __restrict__ Wb3, const float* __restrict__ bb3,
                 const float* __restrict__ Wb4, const float* __restrict__ bb4,
                 const float* __restrict__ Wb5, const float* __restrict__ bb5,
                 const float* __restrict__ Wb6, const float* __restrict__ bb6,
                 float* __restrict__ out, int nrows) {
    extern __shared__ float s[];
    const int p = blockIdx.y;
    const int tid = threadIdx.x;
    const int lane = tid & 31;
    const int warp = tid >> 5;
    const int q = lane & 3;

    // ---- stage weights ----
    stageL<32, 64, true >(s + W_B1, Wb1 + p * 64 * 31, p, tid);
    stageL<64, 32, false>(s + W_B2, Wb2 + p * 32 * 64, p, tid);
    stageL<32, 32, false>(s + W_B3, Wb3 + p * 32 * 32, p, tid);
    stageL<32, 16, false>(s + W_B4, Wb4 + p * 16 * 32, p, tid);
    stageL<64, 32, false>(s + W_A2, Wa2 + p * 32 * 64, p, tid);
    stageL<32, 16, false>(s + W_A3, Wa3 + p * 16 * 32, p, tid);
    cpyf(s + E_BB1, bb1 + p * 64, 64, tid);
    cpyf(s + E_BB2, bb2 + p * 32, 32, tid);
    cpyf(s + E_BB3, bb3 + p * 32, 32, tid);
    cpyf(s + E_BB4, bb4 + p * 16, 16, tid);
    cpyf(s + E_BA2, ba2 + p * 32, 32, tid);
    cpyf(s + E_BA3, ba3 + p * 16, 16, tid);
    cpyf(s + E_WA1, Wa1 + p * 64, 64, tid);
    cpyf(s + E_BA1, ba1 + p * 64, 64, tid);
    cpyf(s + E_WA4, Wa4 + p * 128, 128, tid);
    cpyf(s + E_BA4, ba4 + p * 8, 8, tid);
    cpyf(s + E_WA5, Wa5 + p * 8, 8, tid);
    if (tid < 16) {
        float acc = 0.f;
        for (int o = 0; o < 8; o++)
            acc = fmaf(Wb6[p * 8 + o], Wb5[p * 128 + o * 16 + tid], acc);
        s[E_WEFF + tid] = acc;
    }
    if (tid == 0) {
        float acc = bb6[p];
        for (int o = 0; o < 8; o++)
            acc = fmaf(Wb6[p * 8 + o], bb5[p * 8 + o], acc);
        s[E_BEFF] = acc;
        s[E_BA5] = ba5[p];
    }
    __syncthreads();

    const int NT = nrows >> 4;   // 16-row warp-tiles

    for (int t = blockIdx.x * WARPS + warp; t < NT; t += CPF * WARPS) {
        const int rg = t * 16 + (lane >> 2);   // rows rg and rg+8

        // ======== encoder B ========
        float d1[8][4];
#pragma unroll
        for (int nb = 0; nb < 8; nb++) {
            d1[nb][0] = 0.f; d1[nb][1] = 0.f; d1[nb][2] = 0.f; d1[nb][3] = 0.f;
        }
#pragma unroll
        for (int kb = 0; kb < 4; kb++) {
            uint32_t ah[4], al[4];
            split2(x[rg * 32 + kb * 8 + q],           ah[0], al[0]);
            split2(x[(rg + 8) * 32 + kb * 8 + q],     ah[1], al[1]);
            split2(x[rg * 32 + kb * 8 + q + 4],       ah[2], al[2]);
            split2(x[(rg + 8) * 32 + kb * 8 + q + 4], ah[3], al[3]);
#pragma unroll
            for (int nb = 0; nb < 8; nb++) {
                float4 w = *reinterpret_cast<const float4*>(
                    s + W_B1 + ((kb * 8 + nb) * 32 + lane) * 4);
                uint32_t bh0 = __float_as_uint(w.x), bh1 = __float_as_uint(w.y);
                uint32_t bl0 = __float_as_uint(w.z), bl1 = __float_as_uint(w.w);
                mma8(d1[nb], ah, bh0, bh1);
                mma8(d1[nb], al, bh0, bh1);
                mma8(d1[nb], ah, bl0, bl1);
            }
        }
        biasact<8, 1>(d1, s + E_BB1, lane);
        float d2[4][4];
        layer_stream<8, 4>(s + W_B2, d1, d2, lane);
        biasact<4, 2>(d2, s + E_BB2, lane);
        float d3[4][4];
        layer_stream<4, 4>(s + W_B3, d2, d3, lane);
        biasact<4, 2>(d3, s + E_BB3, lane);
        float d4[2][4];
        layer_stream<4, 2>(s + W_B4, d3, d4, lane);
        biasact<2, 2>(d4, s + E_BB4, lane);
        // collapsed 16->1 dot
        float pg = 0.f, pg8 = 0.f;
#pragma unroll
        for (int nb = 0; nb < 2; nb++) {
            float w0 = s[E_WEFF + nb * 8 + 2 * q];
            float w1 = s[E_WEFF + nb * 8 + 2 * q + 1];
            pg  = fmaf(d4[nb][0], w0, fmaf(d4[nb][1], w1, pg));
            pg8 = fmaf(d4[nb][2], w0, fmaf(d4[nb][3], w1, pg8));
        }
        pg  += __shfl_xor_sync(0xffffffffu, pg, 1);
        pg  += __shfl_xor_sync(0xffffffffu, pg, 2);
        pg8 += __shfl_xor_sync(0xffffffffu, pg8, 1);
        pg8 += __shfl_xor_sync(0xffffffffu, pg8, 2);
        const float bOut_g  = pg + s[E_BEFF];
        const float bOut_g8 = pg8 + s[E_BEFF];

        // ======== encoder A ========
        const float xs_g  = x[rg * 32 + p];
        const float xs_g8 = x[(rg + 8) * 32 + p];
        float dA2[4][4];
#pragma unroll
        for (int nb = 0; nb < 4; nb++) {
            dA2[nb][0] = 0.f; dA2[nb][1] = 0.f; dA2[nb][2] = 0.f; dA2[nb][3] = 0.f;
        }
#pragma unroll
        for (int kb = 0; kb < 8; kb++) {
            int c0 = kb * 8 + q, c1 = c0 + 4;
            uint32_t ah[4], al[4];
            split2(fmaxf(fmaf(s[E_WA1 + c0], xs_g,  s[E_BA1 + c0]), 0.f), ah[0], al[0]);
            split2(fmaxf(fmaf(s[E_WA1 + c0], xs_g8, s[E_BA1 + c0]), 0.f), ah[1], al[1]);
            split2(fmaxf(fmaf(s[E_WA1 + c1], xs_g,  s[E_BA1 + c1]), 0.f), ah[2], al[2]);
            split2(fmaxf(fmaf(s[E_WA1 + c1], xs_g8, s[E_BA1 + c1]), 0.f), ah[3], al[3]);
#pragma unroll
            for (int nb = 0; nb < 4; nb++) {
                float4 w = *reinterpret_cast<const float4*>(
                    s + W_A2 + ((kb * 4 + nb) * 32 + lane) * 4);
                uint32_t bh0 = __float_as_uint(w.x), bh1 = __float_as_uint(w.y);
                uint32_t bl0 = __float_as_uint(w.z), bl1 = __float_as_uint(w.w);
                mma8(dA2[nb], ah, bh0, bh1);
                mma8(dA2[nb], al, bh0, bh1);
                mma8(dA2[nb], ah, bl0, bl1);
            }
        }
        biasact<4, 2>(dA2, s + E_BA2, lane);
        float dA3[2][4];
        layer_stream<4, 2>(s + W_A3, dA2, dA3, lane);
        biasact<2, 2>(dA3, s + E_BA3, lane);
        // A4 (16->8, tanh) + A5 (8->1)
        float accg = s[E_BA5], accg8 = s[E_BA5];
#pragma unroll
        for (int o = 0; o < 8; o++) {
            float sg = 0.f, sg8 = 0.f;
#pragma unroll
            for (int nb = 0; nb < 2; nb++) {
                int c0 = nb * 8 + 2 * q, c1 = c0 + 1;
                float w0 = s[E_WA4 + o * 16 + c0];
                float w1 = s[E_WA4 + o * 16 + c1];
                sg  = fmaf(dA3[nb][0], w0, fmaf(dA3[nb][1], w1, sg));
                sg8 = fmaf(dA3[nb][2], w0, fmaf(dA3[nb][3], w1, sg8));
            }
            sg  += __shfl_xor_sync(0xffffffffu, sg, 1);
            sg  += __shfl_xor_sync(0xffffffffu, sg, 2);
            sg8 += __shfl_xor_sync(0xffffffffu, sg8, 1);
            sg8 += __shfl_xor_sync(0xffffffffu, sg8, 2);
            const float w5 = s[E_WA5 + o], b4 = s[E_BA4 + o];
            accg  = fmaf(w5, fast_tanh(sg + b4), accg);
            accg8 = fmaf(w5, fast_tanh(sg8 + b4), accg8);
        }

        if (q == 0) {
            out[rg * 64 + 2 * p + 0] = accg;
            out[rg * 64 + 2 * p + 1] = bOut_g;
            out[(rg + 8) * 64 + 2 * p + 0] = accg8;
            out[(rg + 8) * 64 + 2 * p + 1] = bOut_g8;
        }
    }
}

extern "C" void kernel_launch(void* const* d_in, const int* in_sizes, int n_in,
                              void* d_out, int out_size) {
    const float* x   = (const float*)d_in[0];
    const float* Wa1 = (const float*)d_in[1];
    const float* ba1 = (const float*)d_in[2];
    const float* Wa2 = (const float*)d_in[3];
    const float* ba2 = (const float*)d_in[4];
    const float* Wa3 = (const float*)d_in[5];
    const float* ba3 = (const float*)d_in[6];
    const float* Wa4 = (const float*)d_in[7];
    const float* ba4 = (const float*)d_in[8];
    const float* Wa5 = (const float*)d_in[9];
    const float* ba5 = (const float*)d_in[10];
    const float* Wb1 = (const float*)d_in[11];
    const float* bb1 = (const float*)d_in[12];
    const float* Wb2 = (const float*)d_in[13];
    const float* bb2 = (const float*)d_in[14];
    const float* Wb3 = (const float*)d_in[15];
    const float* bb3 = (const float*)d_in[16];
    const float* Wb4 = (const float*)d_in[17];
    const float* bb4 = (const float*)d_in[18];
    const float* Wb5 = (const float*)d_in[19];
    const float* bb5 = (const float*)d_in[20];
    const float* Wb6 = (const float*)d_in[21];
    const float* bb6 = (const float*)d_in[22];
    float* out = (float*)d_out;

    const int nrows = in_sizes[0] / PFEAT;
    const size_t smemBytes = SMEM_FLOATS * sizeof(float);
    cudaFuncSetAttribute(mlp32_mma_kernel,
                         cudaFuncAttributeMaxDynamicSharedMemorySize,
                         (int)smemBytes);
    dim3 grid(CPF, PFEAT);
    mlp32_mma_kernel<<<grid, NTHREADS, smemBytes>>>(
        x, Wa1, ba1, Wa2, ba2, Wa3, ba3, Wa4, ba4, Wa5, ba5,
        Wb1, bb1, Wb2, bb2, Wb3, bb3, Wb4, bb4, Wb5, bb5, Wb6, bb6,
        out, nrows);
}

// round 12
// speedup vs baseline: 2.0798x; 1.0609x over previous
#include <cuda_runtime.h>
#include <cuda_bf16.h>
#include <cstdint>

#define NTHREADS 256
#define WARPS 8
#define PFEAT 32
#define CPF 9               // 288 CTAs total (single wave at 2 CTA/SM)

// ---- smem float-index offsets ----
// weight planes: per (kb,nb) block, per lane: float4 {wh0, wh1, wl0, wl1}
#define W_B1 0        // KB4 NB8 -> 4096
#define W_B2 4096     // KB8 NB4 -> 4096
#define W_B3 8192     // KB4 NB4 -> 2048
#define W_B4 10240    // KB4 NB2 -> 1024
#define W_A2 11264    // KB8 NB4 -> 4096
#define W_A3 15360    // KB4 NB2 -> 1024
#define E_BB1 16384
#define E_BB2 16448
#define E_BB3 16480
#define E_BB4 16512
#define E_BA2 16528
#define E_BA3 16560
#define E_WEFF 16576
#define E_BEFF 16592
#define E_WA1 16596
#define E_BA1 16660
#define E_WA4 16724
#define E_BA4 16852
#define E_WA5 16860
#define E_BA5 16868
#define SMEM_FLOATS 16872

__device__ __forceinline__ float fast_tanh(float x) {
    float r; asm("tanh.approx.f32 %0, %1;" : "=f"(r) : "f"(x)); return r;
}
// tf32 split via truncation: hi = v masked to tf32 bits, lo = v - hi (exact).
__device__ __forceinline__ void split2(float v, uint32_t& h, uint32_t& l) {
    uint32_t hv = __float_as_uint(v) & 0xffffe000u;
    h = hv;
    l = __float_as_uint(v - __uint_as_float(hv));
}
__device__ __forceinline__ void mma8(float* d, const uint32_t* a,
                                     uint32_t b0, uint32_t b1) {
    asm volatile(
        "mma.sync.aligned.m16n8k8.row.col.f32.tf32.tf32.f32 "
        "{%0,%1,%2,%3}, {%4,%5,%6,%7}, {%8,%9}, {%0,%1,%2,%3};"
        : "+f"(d[0]), "+f"(d[1]), "+f"(d[2]), "+f"(d[3])
        : "r"(a[0]), "r"(a[1]), "r"(a[2]), "r"(a[3]), "r"(b0), "r"(b1));
}

// bias + activation on D frags. ACT: 1 relu, 2 tanh
template<int NB, int ACT>
__device__ __forceinline__ void biasact(float (*d)[4],
                                        const float* __restrict__ bias, int lane) {
    const int q = lane & 3;
#pragma unroll
    for (int nb = 0; nb < NB; nb++) {
        float b0 = bias[nb * 8 + 2 * q], b1 = bias[nb * 8 + 2 * q + 1];
        float v0 = d[nb][0] + b0, v1 = d[nb][1] + b1;
        float v2 = d[nb][2] + b0, v3 = d[nb][3] + b1;
        if (ACT == 1) { v0 = fmaxf(v0, 0.f); v1 = fmaxf(v1, 0.f);
                        v2 = fmaxf(v2, 0.f); v3 = fmaxf(v3, 0.f); }
        if (ACT == 2) { v0 = fast_tanh(v0); v1 = fast_tanh(v1);
                        v2 = fast_tanh(v2); v3 = fast_tanh(v3); }
        d[nb][0] = v0; d[nb][1] = v1; d[nb][2] = v2; d[nb][3] = v3;
    }
}

// one D block (m16n8) -> one A block (m16k8) + split
__device__ __forceinline__ void refrag1(const float* dj, uint32_t* ah,
                                        uint32_t* al, int lane) {
    const int q = lane & 3;
    const int s0 = (lane & ~3) | (q >> 1);
    const int s2 = s0 + 2;
    const bool odd = (q & 1) != 0;
    float c0 = dj[0], c1 = dj[1], c2 = dj[2], c3 = dj[3];
    float t00 = __shfl_sync(0xffffffffu, c0, s0);
    float t10 = __shfl_sync(0xffffffffu, c1, s0);
    float t02 = __shfl_sync(0xffffffffu, c0, s2);
    float t12 = __shfl_sync(0xffffffffu, c1, s2);
    float t20 = __shfl_sync(0xffffffffu, c2, s0);
    float t30 = __shfl_sync(0xffffffffu, c3, s0);
    float t22 = __shfl_sync(0xffffffffu, c2, s2);
    float t32 = __shfl_sync(0xffffffffu, c3, s2);
    float a0 = odd ? t10 : t00;
    float a2 = odd ? t12 : t02;
    float a1 = odd ? t30 : t20;
    float a3 = odd ? t32 : t22;
    split2(a0, ah[0], al[0]);
    split2(a1, ah[1], al[1]);
    split2(a2, ah[2], al[2]);
    split2(a3, ah[3], al[3]);
}

// streamed layer, TWO 16-row halves share every weight load
template<int KB, int NB>
__device__ __forceinline__ void layer_stream2(const float* __restrict__ wp,
                                              const float (*dpa)[4],
                                              const float (*dpb)[4],
                                              float (*dna)[4], float (*dnb)[4],
                                              int lane) {
#pragma unroll
    for (int nb = 0; nb < NB; nb++) {
        dna[nb][0] = 0.f; dna[nb][1] = 0.f; dna[nb][2] = 0.f; dna[nb][3] = 0.f;
        dnb[nb][0] = 0.f; dnb[nb][1] = 0.f; dnb[nb][2] = 0.f; dnb[nb][3] = 0.f;
    }
#pragma unroll
    for (int j = 0; j < KB; j++) {
        uint32_t aha[4], ala[4], ahb[4], alb[4];
        refrag1(dpa[j], aha, ala, lane);
        refrag1(dpb[j], ahb, alb, lane);
#pragma unroll
        for (int nb = 0; nb < NB; nb++) {
            float4 w = *reinterpret_cast<const float4*>(
                wp + ((j * NB + nb) * 32 + lane) * 4);
            uint32_t bh0 = __float_as_uint(w.x), bh1 = __float_as_uint(w.y);
            uint32_t bl0 = __float_as_uint(w.z), bl1 = __float_as_uint(w.w);
            mma8(dna[nb], aha, bh0, bh1);
            mma8(dnb[nb], ahb, bh0, bh1);
            mma8(dna[nb], ala, bh0, bh1);
            mma8(dnb[nb], alb, bh0, bh1);
            mma8(dna[nb], aha, bl0, bl1);
            mma8(dnb[nb], ahb, bl0, bl1);
        }
    }
}

// stage one layer's weights, interleaved hi/lo float4 layout
template<int IN, int OUT, bool LOO>
__device__ void stageL(float* wp, const float* __restrict__ W, int p, int tid) {
    constexpr int NB = OUT / 8;
    constexpr int KB = IN / 8;
    for (int idx = tid; idx < KB * NB * 64; idx += NTHREADS) {
        int blk = idx >> 6;
        int r = idx & 63;
        int lane = r >> 1, b = r & 1;
        int nb = blk % NB;
        int kb = blk / NB;
        int n = nb * 8 + (lane >> 2);
        int k = kb * 8 + (lane & 3) + 4 * b;
        float w;
        if (LOO) w = (k == p) ? 0.f : W[n * 31 + (k < p ? k : k - 1)];
        else     w = W[n * IN + k];
        uint32_t h, l;
        split2(w, h, l);
        wp[blk * 128 + lane * 4 + b] = __uint_as_float(h);
        wp[blk * 128 + lane * 4 + 2 + b] = __uint_as_float(l);
    }
}

__device__ __forceinline__ void cpyf(float* dst, const float* __restrict__ src,
                                     int n, int tid) {
    for (int i = tid; i < n; i += NTHREADS) dst[i] = src[i];
}

__global__ void __launch_bounds__(NTHREADS, 2)
mlp32_mma_kernel(const float* __restrict__ x,
                 const float* __restrict__ Wa1, const float* __restrict__ ba1,
                 const float* __restrict__ Wa2, const float* __restrict__ ba2,
                 const float* __restrict__ Wa3, const float* __restrict__ ba3,
                 const float* __restrict__ Wa4, const float* __restrict__ ba4,
                 const float* __restrict__ Wa5, const float* __restrict__ ba5,
                 const float* __restrict__ Wb1, const float* __restrict__ bb1,
                 const float* __restrict__ Wb2, const float* __restrict__ bb2,
                 const float* __restrict__ Wb3, const float* __restrict__ bb3,
                 const float* __restrict__ Wb4, const float* __restrict__ bb4,
                 const float* __restrict__ Wb5, const float* __restrict__ bb5,
                 const float* __restrict__ Wb6, const float* __restrict__ bb6,
                 float* __restrict__ out, int nrows) {
    extern __shared__ float s[];
    const int p = blockIdx.y;
    const int tid = threadIdx.x;
    const int lane = tid & 31;
    const int warp = tid >> 5;
    const int q = lane & 3;

    // ---- stage weights ----
    stageL<32, 64, true >(s + W_B1, Wb1 + p * 64 * 31, p, tid);
    stageL<64, 32, false>(s + W_B2, Wb2 + p * 32 * 64, p, tid);
    stageL<32, 32, false>(s + W_B3, Wb3 + p * 32 * 32, p, tid);
    stageL<32, 16, false>(s + W_B4, Wb4 + p * 16 * 32, p, tid);
    stageL<64, 32, false>(s + W_A2, Wa2 + p * 32 * 64, p, tid);
    stageL<32, 16, false>(s + W_A3, Wa3 + p * 16 * 32, p, tid);
    cpyf(s + E_BB1, bb1 + p * 64, 64, tid);
    cpyf(s + E_BB2, bb2 + p * 32, 32, tid);
    cpyf(s + E_BB3, bb3 + p * 32, 32, tid);
    cpyf(s + E_BB4, bb4 + p * 16, 16, tid);
    cpyf(s + E_BA2, ba2 + p * 32, 32, tid);
    cpyf(s + E_BA3, ba3 + p * 16, 16, tid);
    cpyf(s + E_WA1, Wa1 + p * 64, 64, tid);
    cpyf(s + E_BA1, ba1 + p * 64, 64, tid);
    cpyf(s + E_WA4, Wa4 + p * 128, 128, tid);
    cpyf(s + E_BA4, ba4 + p * 8, 8, tid);
    cpyf(s + E_WA5, Wa5 + p * 8, 8, tid);
    if (tid < 16) {
        float acc = 0.f;
        for (int o = 0; o < 8; o++)
            acc = fmaf(Wb6[p * 8 + o], Wb5[p * 128 + o * 16 + tid], acc);
        s[E_WEFF + tid] = acc;
    }
    if (tid == 0) {
        float acc = bb6[p];
        for (int o = 0; o < 8; o++)
            acc = fmaf(Wb6[p * 8 + o], bb5[p * 8 + o], acc);
        s[E_BEFF] = acc;
        s[E_BA5] = ba5[p];
    }
    __syncthreads();

    const int NT = nrows >> 5;   // 32-row warp-tiles

    for (int t = blockIdx.x * WARPS + warp; t < NT; t += CPF * WARPS) {
        const int rga = t * 32 + (lane >> 2);   // half a: rows rga, rga+8
        const int rgb = rga + 16;               // half b: rows rgb, rgb+8

        // ======== encoder B : layer1 (32->64 relu), both halves ========
        float d1a[8][4], d1b[8][4];
#pragma unroll
        for (int nb = 0; nb < 8; nb++) {
            d1a[nb][0] = 0.f; d1a[nb][1] = 0.f; d1a[nb][2] = 0.f; d1a[nb][3] = 0.f;
            d1b[nb][0] = 0.f; d1b[nb][1] = 0.f; d1b[nb][2] = 0.f; d1b[nb][3] = 0.f;
        }
#pragma unroll
        for (int kb = 0; kb < 4; kb++) {
            uint32_t aha[4], ala[4], ahb[4], alb[4];
            split2(x[rga * 32 + kb * 8 + q],           aha[0], ala[0]);
            split2(x[(rga + 8) * 32 + kb * 8 + q],     aha[1], ala[1]);
            split2(x[rga * 32 + kb * 8 + q + 4],       aha[2], ala[2]);
            split2(x[(rga + 8) * 32 + kb * 8 + q + 4], aha[3], ala[3]);
            split2(x[rgb * 32 + kb * 8 + q],           ahb[0], alb[0]);
            split2(x[(rgb + 8) * 32 + kb * 8 + q],     ahb[1], alb[1]);
            split2(x[rgb * 32 + kb * 8 + q + 4],       ahb[2], alb[2]);
            split2(x[(rgb + 8) * 32 + kb * 8 + q + 4], ahb[3], alb[3]);
#pragma unroll
            for (int nb = 0; nb < 8; nb++) {
                float4 w = *reinterpret_cast<const float4*>(
                    s + W_B1 + ((kb * 8 + nb) * 32 + lane) * 4);
                uint32_t bh0 = __float_as_uint(w.x), bh1 = __float_as_uint(w.y);
                uint32_t bl0 = __float_as_uint(w.z), bl1 = __float_as_uint(w.w);
                mma8(d1a[nb], aha, bh0, bh1);
                mma8(d1b[nb], ahb, bh0, bh1);
                mma8(d1a[nb], ala, bh0, bh1);
                mma8(d1b[nb], alb, bh0, bh1);
                mma8(d1a[nb], aha, bl0, bl1);
                mma8(d1b[nb], ahb, bl0, bl1);
            }
        }
        biasact<8, 1>(d1a, s + E_BB1, lane);
        biasact<8, 1>(d1b, s + E_BB1, lane);
        float d2a[4][4], d2b[4][4];
        layer_stream2<8, 4>(s + W_B2, d1a, d1b, d2a, d2b, lane);
        biasact<4, 2>(d2a, s + E_BB2, lane);
        biasact<4, 2>(d2b, s + E_BB2, lane);
        float d3a[4][4], d3b[4][4];
        layer_stream2<4, 4>(s + W_B3, d2a, d2b, d3a, d3b, lane);
        biasact<4, 2>(d3a, s + E_BB3, lane);
        biasact<4, 2>(d3b, s + E_BB3, lane);
        float d4a[2][4], d4b[2][4];
        layer_stream2<4, 2>(s + W_B4, d3a, d3b, d4a, d4b, lane);
        biasact<2, 2>(d4a, s + E_BB4, lane);
        biasact<2, 2>(d4b, s + E_BB4, lane);
        // collapsed 16->1 dot, both halves
        float pa = 0.f, pa8 = 0.f, pb = 0.f, pb8 = 0.f;
#pragma unroll
        for (int nb = 0; nb < 2; nb++) {
            float w0 = s[E_WEFF + nb * 8 + 2 * q];
            float w1 = s[E_WEFF + nb * 8 + 2 * q + 1];
            pa  = fmaf(d4a[nb][0], w0, fmaf(d4a[nb][1], w1, pa));
            pa8 = fmaf(d4a[nb][2], w0, fmaf(d4a[nb][3], w1, pa8));
            pb  = fmaf(d4b[nb][0], w0, fmaf(d4b[nb][1], w1, pb));
            pb8 = fmaf(d4b[nb][2], w0, fmaf(d4b[nb][3], w1, pb8));
        }
        pa  += __shfl_xor_sync(0xffffffffu, pa, 1);
        pa  += __shfl_xor_sync(0xffffffffu, pa, 2);
        pa8 += __shfl_xor_sync(0xffffffffu, pa8, 1);
        pa8 += __shfl_xor_sync(0xffffffffu, pa8, 2);
        pb  += __shfl_xor_sync(0xffffffffu, pb, 1);
        pb  += __shfl_xor_sync(0xffffffffu, pb, 2);
        pb8 += __shfl_xor_sync(0xffffffffu, pb8, 1);
        pb8 += __shfl_xor_sync(0xffffffffu, pb8, 2);
        const float bO_a  = pa + s[E_BEFF];
        const float bO_a8 = pa8 + s[E_BEFF];
        const float bO_b  = pb + s[E_BEFF];
        const float bO_b8 = pb8 + s[E_BEFF];

        // ======== encoder A ========
        const float xsa  = x[rga * 32 + p];
        const float xsa8 = x[(rga + 8) * 32 + p];
        const float xsb  = x[rgb * 32 + p];
        const float xsb8 = x[(rgb + 8) * 32 + p];
        float dA2a[4][4], dA2b[4][4];
#pragma unroll
        for (int nb = 0; nb < 4; nb++) {
            dA2a[nb][0] = 0.f; dA2a[nb][1] = 0.f; dA2a[nb][2] = 0.f; dA2a[nb][3] = 0.f;
            dA2b[nb][0] = 0.f; dA2b[nb][1] = 0.f; dA2b[nb][2] = 0.f; dA2b[nb][3] = 0.f;
        }
#pragma unroll
        for (int kb = 0; kb < 8; kb++) {
            int c0 = kb * 8 + q, c1 = c0 + 4;
            float w10 = s[E_WA1 + c0], b10 = s[E_BA1 + c0];
            float w11 = s[E_WA1 + c1], b11 = s[E_BA1 + c1];
            uint32_t aha[4], ala[4], ahb[4], alb[4];
            split2(fmaxf(fmaf(w10, xsa,  b10), 0.f), aha[0], ala[0]);
            split2(fmaxf(fmaf(w10, xsa8, b10), 0.f), aha[1], ala[1]);
            split2(fmaxf(fmaf(w11, xsa,  b11), 0.f), aha[2], ala[2]);
            split2(fmaxf(fmaf(w11, xsa8, b11), 0.f), aha[3], ala[3]);
            split2(fmaxf(fmaf(w10, xsb,  b10), 0.f), ahb[0], alb[0]);
            split2(fmaxf(fmaf(w10, xsb8, b10), 0.f), ahb[1], alb[1]);
            split2(fmaxf(fmaf(w11, xsb,  b11), 0.f), ahb[2], alb[2]);
            split2(fmaxf(fmaf(w11, xsb8, b11), 0.f), ahb[3], alb[3]);
#pragma unroll
            for (int nb = 0; nb < 4; nb++) {
                float4 w = *reinterpret_cast<const float4*>(
                    s + W_A2 + ((kb * 4 + nb) * 32 + lane) * 4);
                uint32_t bh0 = __float_as_uint(w.x), bh1 = __float_as_uint(w.y);
                uint32_t bl0 = __float_as_uint(w.z), bl1 = __float_as_uint(w.w);
                mma8(dA2a[nb], aha, bh0, bh1);
                mma8(dA2b[nb], ahb, bh0, bh1);
                mma8(dA2a[nb], ala, bh0, bh1);
                mma8(dA2b[nb], alb, bh0, bh1);
                mma8(dA2a[nb], aha, bl0, bl1);
                mma8(dA2b[nb], ahb, bl0, bl1);
            }
        }
        biasact<4, 2>(dA2a, s + E_BA2, lane);
        biasact<4, 2>(dA2b, s + E_BA2, lane);
        float dA3a[2][4], dA3b[2][4];
        layer_stream2<4, 2>(s + W_A3, dA2a, dA2b, dA3a, dA3b, lane);
        biasact<2, 2>(dA3a, s + E_BA3, lane);
        biasact<2, 2>(dA3b, s + E_BA3, lane);
        // A4 (16->8, tanh) + A5 (8->1), both halves
        float aO_a = s[E_BA5], aO_a8 = s[E_BA5];
        float aO_b = s[E_BA5], aO_b8 = s[E_BA5];
#pragma unroll
        for (int o = 0; o < 8; o++) {
            float sa = 0.f, sa8 = 0.f, sb = 0.f, sb8 = 0.f;
#pragma unroll
            for (int nb = 0; nb < 2; nb++) {
                int c0 = nb * 8 + 2 * q, c1 = c0 + 1;
                float w0 = s[E_WA4 + o * 16 + c0];
                float w1 = s[E_WA4 + o * 16 + c1];
                sa  = fmaf(dA3a[nb][0], w0, fmaf(dA3a[nb][1], w1, sa));
                sa8 = fmaf(dA3a[nb][2], w0, fmaf(dA3a[nb][3], w1, sa8));
                sb  = fmaf(dA3b[nb][0], w0, fmaf(dA3b[nb][1], w1, sb));
                sb8 = fmaf(dA3b[nb][2], w0, fmaf(dA3b[nb][3], w1, sb8));
            }
            sa  += __shfl_xor_sync(0xffffffffu, sa, 1);
            sa  += __shfl_xor_sync(0xffffffffu, sa, 2);
            sa8 += __shfl_xor_sync(0xffffffffu, sa8, 1);
            sa8 += __shfl_xor_sync(0xffffffffu, sa8, 2);
            sb  += __shfl_xor_sync(0xffffffffu, sb, 1);
            sb  += __shfl_xor_sync(0xffffffffu, sb, 2);
            sb8 += __shfl_xor_sync(0xffffffffu, sb8, 1);
            sb8 += __shfl_xor_sync(0xffffffffu, sb8, 2);
            const float w5 = s[E_WA5 + o], b4 = s[E_BA4 + o];
            aO_a  = fmaf(w5, fast_tanh(sa + b4), aO_a);
            aO_a8 = fmaf(w5, fast_tanh(sa8 + b4), aO_a8);
            aO_b  = fmaf(w5, fast_tanh(sb + b4), aO_b);
            aO_b8 = fmaf(w5, fast_tanh(sb8 + b4), aO_b8);
        }

        if (q == 0) {
            out[rga * 64 + 2 * p + 0] = aO_a;
            out[rga * 64 + 2 * p + 1] = bO_a;
            out[(rga + 8) * 64 + 2 * p + 0] = aO_a8;
            out[(rga + 8) * 64 + 2 * p + 1] = bO_a8;
            out[rgb * 64 + 2 * p + 0] = aO_b;
            out[rgb * 64 + 2 * p + 1] = bO_b;
            out[(rgb + 8) * 64 + 2 * p + 0] = aO_b8;
            out[(rgb + 8) * 64 + 2 * p + 1] = bO_b8;
        }
    }
}

extern "C" void kernel_launch(void* const* d_in, const int* in_sizes, int n_in,
                              void* d_out, int out_size) {
    const float* x   = (const float*)d_in[0];
    const float* Wa1 = (const float*)d_in[1];
    const float* ba1 = (const float*)d_in[2];
    const float* Wa2 = (const float*)d_in[3];
    const float* ba2 = (const float*)d_in[4];
    const float* Wa3 = (const float*)d_in[5];
    const float* ba3 = (const float*)d_in[6];
    const float* Wa4 = (const float*)d_in[7];
    const float* ba4 = (const float*)d_in[8];
    const float* Wa5 = (const float*)d_in[9];
    const float* ba5 = (const float*)d_in[10];
    const float* Wb1 = (const float*)d_in[11];
    const float* bb1 = (const float*)d_in[12];
    const float* Wb2 = (const float*)d_in[13];
    const float* bb2 = (const float*)d_in[14];
    const float* Wb3 = (const float*)d_in[15];
    const float* bb3 = (const float*)d_in[16];
    const float* Wb4 = (const float*)d_in[17];
    const float* bb4 = (const float*)d_in[18];
    const float* Wb5 = (const float*)d_in[19];
    const float* bb5 = (const float*)d_in[20];
    const float* Wb6 = (const float*)d_in[21];
    const float* bb6 = (const float*)d_in[22];
    float* out = (float*)d_out;

    const int nrows = in_sizes[0] / PFEAT;
    const size_t smemBytes = SMEM_FLOATS * sizeof(float);
    cudaFuncSetAttribute(mlp32_mma_kernel,
                         cudaFuncAttributeMaxDynamicSharedMemorySize,
                         (int)smemBytes);
    dim3 grid(CPF, PFEAT);
    mlp32_mma_kernel<<<grid, NTHREADS, smemBytes>>>(
        x, Wa1, ba1, Wa2, ba2, Wa3, ba3, Wa4, ba4, Wa5, ba5,
        Wb1, bb1, Wb2, bb2, Wb3, bb3, Wb4, bb4, Wb5, bb5, Wb6, bb6,
        out, nrows);
}

// round 15
// speedup vs baseline: 3.4949x; 1.6804x over previous
#include <cuda_runtime.h>
#include <cuda_bf16.h>
#include <cstdint>

#define NTHREADS 256
#define WARPS 8
#define PFEAT 32
#define CPF 9               // 288 CTAs total (single wave at 2 CTA/SM)

// ---- smem float-index offsets ----
// weight blocks (bf16 k16): per (kb,nb) block, per lane: uint4 {bh0, bh1, bl0, bl1}
#define W_B1 0        // KB2 NB8 -> 2048
#define W_B2 2048     // KB4 NB4 -> 2048
#define W_B3 4096     // KB2 NB4 -> 1024
#define W_B4 5120     // KB2 NB2 -> 512
#define W_A2 5632     // KB4 NB4 -> 2048
#define W_A3 7680     // KB2 NB2 -> 512
#define E_BB1 8192
#define E_BB2 8256
#define E_BB3 8288
#define E_BB4 8320
#define E_BA2 8336
#define E_BA3 8368
#define E_WEFF 8384
#define E_BEFF 8400
#define E_WA1 8404
#define E_BA1 8468
#define E_WA4 8532
#define E_BA4 8660
#define E_WA5 8668
#define E_BA5 8676
#define SMEM_FLOATS 8680

__device__ __forceinline__ float fast_tanh(float x) {
    float r; asm("tanh.approx.f32 %0, %1;" : "=f"(r) : "f"(x)); return r;
}
// pack two floats as bf16x2: v0 -> low half, v1 -> high half
__device__ __forceinline__ uint32_t packbf(float v0, float v1) {
    uint32_t d;
    asm("cvt.rn.bf16x2.f32 %0, %1, %2;" : "=r"(d) : "f"(v1), "f"(v0));
    return d;
}
// split pair (v0,v1) into hi bf16x2 + lo bf16x2 (lo = exact residual, bf16-rounded)
__device__ __forceinline__ void split_bf2(float v0, float v1,
                                          uint32_t& h, uint32_t& l) {
    uint32_t hp = packbf(v0, v1);
    float h0 = __uint_as_float(hp << 16);
    float h1 = __uint_as_float(hp & 0xffff0000u);
    h = hp;
    l = packbf(v0 - h0, v1 - h1);
}
__device__ __forceinline__ void mma16(float* d, const uint32_t* a,
                                      uint32_t b0, uint32_t b1) {
    asm volatile(
        "mma.sync.aligned.m16n8k16.row.col.f32.bf16.bf16.f32 "
        "{%0,%1,%2,%3}, {%4,%5,%6,%7}, {%8,%9}, {%0,%1,%2,%3};"
        : "+f"(d[0]), "+f"(d[1]), "+f"(d[2]), "+f"(d[3])
        : "r"(a[0]), "r"(a[1]), "r"(a[2]), "r"(a[3]), "r"(b0), "r"(b1));
}

// bias + activation on D frags. ACT: 1 relu, 2 tanh
template<int NB, int ACT>
__device__ __forceinline__ void biasact(float (*d)[4],
                                        const float* __restrict__ bias, int lane) {
    const int q = lane & 3;
#pragma unroll
    for (int nb = 0; nb < NB; nb++) {
        float b0 = bias[nb * 8 + 2 * q], b1 = bias[nb * 8 + 2 * q + 1];
        float v0 = d[nb][0] + b0, v1 = d[nb][1] + b1;
        float v2 = d[nb][2] + b0, v3 = d[nb][3] + b1;
        if (ACT == 1) { v0 = fmaxf(v0, 0.f); v1 = fmaxf(v1, 0.f);
                        v2 = fmaxf(v2, 0.f); v3 = fmaxf(v3, 0.f); }
        if (ACT == 2) { v0 = fast_tanh(v0); v1 = fast_tanh(v1);
                        v2 = fast_tanh(v2); v3 = fast_tanh(v3); }
        d[nb][0] = v0; d[nb][1] = v1; d[nb][2] = v2; d[nb][3] = v3;
    }
}

// two D blocks (8 cols each) -> one bf16 A block (16 cols), lane-identical (NO shuffles)
__device__ __forceinline__ void d2a(const float* dj0, const float* dj1,
                                    uint32_t* ah, uint32_t* al) {
    split_bf2(dj0[0], dj0[1], ah[0], al[0]);
    split_bf2(dj0[2], dj0[3], ah[1], al[1]);
    split_bf2(dj1[0], dj1[1], ah[2], al[2]);
    split_bf2(dj1[2], dj1[3], ah[3], al[3]);
}

// streamed bf16 layer, TWO 16-row halves share every weight load.
// KBB = number of 16-col A blocks (prev layer has 2*KBB D blocks).
template<int KBB, int NB>
__device__ __forceinline__ void layer_stream2(const float* __restrict__ wp,
                                              const float (*dpa)[4],
                                              const float (*dpb)[4],
                                              float (*dna)[4], float (*dnb)[4],
                                              int lane) {
#pragma unroll
    for (int nb = 0; nb < NB; nb++) {
        dna[nb][0] = 0.f; dna[nb][1] = 0.f; dna[nb][2] = 0.f; dna[nb][3] = 0.f;
        dnb[nb][0] = 0.f; dnb[nb][1] = 0.f; dnb[nb][2] = 0.f; dnb[nb][3] = 0.f;
    }
#pragma unroll
    for (int j = 0; j < KBB; j++) {
        uint32_t aha[4], ala[4], ahb[4], alb[4];
        d2a(dpa[2 * j], dpa[2 * j + 1], aha, ala);
        d2a(dpb[2 * j], dpb[2 * j + 1], ahb, alb);
#pragma unroll
        for (int nb = 0; nb < NB; nb++) {
            float4 w = *reinterpret_cast<const float4*>(
                wp + ((j * NB + nb) * 32 + lane) * 4);
            uint32_t bh0 = __float_as_uint(w.x), bh1 = __float_as_uint(w.y);
            uint32_t bl0 = __float_as_uint(w.z), bl1 = __float_as_uint(w.w);
            mma16(dna[nb], aha, bh0, bh1);
            mma16(dnb[nb], ahb, bh0, bh1);
            mma16(dna[nb], ala, bh0, bh1);
            mma16(dnb[nb], alb, bh0, bh1);
            mma16(dna[nb], aha, bl0, bl1);
            mma16(dnb[nb], ahb, bl0, bl1);
        }
    }
}

// stage one layer's weights as bf16 hi/lo, m16n8k16 B layout
template<int IN, int OUT, bool LOO>
__device__ void stageL(float* wp, const float* __restrict__ W, int p, int tid) {
    constexpr int KB = IN / 16, NB = OUT / 8;
    for (int e = tid; e < KB * NB * 32; e += NTHREADS) {
        int blk = e >> 5, lane = e & 31;
        int kb = blk / NB, nb = blk % NB;
        int n = nb * 8 + (lane >> 2);
        int k0 = kb * 16 + 2 * (lane & 3);
        float w00, w01, w08, w09;
        if (LOO) {
            w00 = (k0 == p)     ? 0.f : W[n * 31 + (k0 < p ? k0 : k0 - 1)];
            w01 = (k0 + 1 == p) ? 0.f : W[n * 31 + (k0 + 1 < p ? k0 + 1 : k0)];
            w08 = (k0 + 8 == p) ? 0.f : W[n * 31 + (k0 + 8 < p ? k0 + 8 : k0 + 7)];
            w09 = (k0 + 9 == p) ? 0.f : W[n * 31 + (k0 + 9 < p ? k0 + 9 : k0 + 8)];
        } else {
            w00 = W[n * IN + k0];     w01 = W[n * IN + k0 + 1];
            w08 = W[n * IN + k0 + 8]; w09 = W[n * IN + k0 + 9];
        }
        uint32_t bh0, bl0, bh1, bl1;
        split_bf2(w00, w01, bh0, bl0);
        split_bf2(w08, w09, bh1, bl1);
        float4* dst = reinterpret_cast<float4*>(wp + (blk * 32 + lane) * 4);
        *dst = make_float4(__uint_as_float(bh0), __uint_as_float(bh1),
                           __uint_as_float(bl0), __uint_as_float(bl1));
    }
}

__device__ __forceinline__ void cpyf(float* dst, const float* __restrict__ src,
                                     int n, int tid) {
    for (int i = tid; i < n; i += NTHREADS) dst[i] = src[i];
}

__global__ void __launch_bounds__(NTHREADS, 2)
mlp32_mma_kernel(const float* __restrict__ x,
                 const float* __restrict__ Wa1, const float* __restrict__ ba1,
                 const float* __restrict__ Wa2, const float* __restrict__ ba2,
                 const float* __restrict__ Wa3, const float* __restrict__ ba3,
                 const float* __restrict__ Wa4, const float* __restrict__ ba4,
                 const float* __restrict__ Wa5, const float* __restrict__ ba5,
                 const float* __restrict__ Wb1, const float* __restrict__ bb1,
                 const float* __restrict__ Wb2, const float* __restrict__ bb2,
                 const float* __restrict__ Wb3, const float* __restrict__ bb3,
                 const float* __restrict__ Wb4, const float* __restrict__ bb4,
                 const float* __restrict__ Wb5, const float* __restrict__ bb5,
                 const float* __restrict__ Wb6, const float* __restrict__ bb6,
                 float* __restrict__ out, int nrows) {
    extern __shared__ float s[];
    const int p = blockIdx.y;
    const int tid = threadIdx.x;
    const int lane = tid & 31;
    const int warp = tid >> 5;
    const int q = lane & 3;

    // ---- stage weights ----
    stageL<32, 64, true >(s + W_B1, Wb1 + p * 64 * 31, p, tid);
    stageL<64, 32, false>(s + W_B2, Wb2 + p * 32 * 64, p, tid);
    stageL<32, 32, false>(s + W_B3, Wb3 + p * 32 * 32, p, tid);
    stageL<32, 16, false>(s + W_B4, Wb4 + p * 16 * 32, p, tid);
    stageL<64, 32, false>(s + W_A2, Wa2 + p * 32 * 64, p, tid);
    stageL<32, 16, false>(s + W_A3, Wa3 + p * 16 * 32, p, tid);
    cpyf(s + E_BB1, bb1 + p * 64, 64, tid);
    cpyf(s + E_BB2, bb2 + p * 32, 32, tid);
    cpyf(s + E_BB3, bb3 + p * 32, 32, tid);
    cpyf(s + E_BB4, bb4 + p * 16, 16, tid);
    cpyf(s + E_BA2, ba2 + p * 32, 32, tid);
    cpyf(s + E_BA3, ba3 + p * 16, 16, tid);
    cpyf(s + E_WA1, Wa1 + p * 64, 64, tid);
    cpyf(s + E_BA1, ba1 + p * 64, 64, tid);
    cpyf(s + E_WA4, Wa4 + p * 128, 128, tid);
    cpyf(s + E_BA4, ba4 + p * 8, 8, tid);
    cpyf(s + E_WA5, Wa5 + p * 8, 8, tid);
    if (tid < 16) {
        float acc = 0.f;
        for (int o = 0; o < 8; o++)
            acc = fmaf(Wb6[p * 8 + o], Wb5[p * 128 + o * 16 + tid], acc);
        s[E_WEFF + tid] = acc;
    }
    if (tid == 0) {
        float acc = bb6[p];
        for (int o = 0; o < 8; o++)
            acc = fmaf(Wb6[p * 8 + o], bb5[p * 8 + o], acc);
        s[E_BEFF] = acc;
        s[E_BA5] = ba5[p];
    }
    __syncthreads();

    const int NT = nrows >> 5;   // 32-row warp-tiles

    for (int t = blockIdx.x * WARPS + warp; t < NT; t += CPF * WARPS) {
        const int rga = t * 32 + (lane >> 2);   // half a: rows rga, rga+8
        const int rgb = rga + 16;               // half b

        // ======== encoder B : layer1 (32->64 relu), both halves ========
        float d1a[8][4], d1b[8][4];
#pragma unroll
        for (int nb = 0; nb < 8; nb++) {
            d1a[nb][0] = 0.f; d1a[nb][1] = 0.f; d1a[nb][2] = 0.f; d1a[nb][3] = 0.f;
            d1b[nb][0] = 0.f; d1b[nb][1] = 0.f; d1b[nb][2] = 0.f; d1b[nb][3] = 0.f;
        }
#pragma unroll
        for (int kb = 0; kb < 2; kb++) {
            const int c0 = kb * 16 + 2 * q;
            uint32_t aha[4], ala[4], ahb[4], alb[4];
            split_bf2(x[rga * 32 + c0],           x[rga * 32 + c0 + 1],       aha[0], ala[0]);
            split_bf2(x[(rga + 8) * 32 + c0],     x[(rga + 8) * 32 + c0 + 1], aha[1], ala[1]);
            split_bf2(x[rga * 32 + c0 + 8],       x[rga * 32 + c0 + 9],       aha[2], ala[2]);
            split_bf2(x[(rga + 8) * 32 + c0 + 8], x[(rga + 8) * 32 + c0 + 9], aha[3], ala[3]);
            split_bf2(x[rgb * 32 + c0],           x[rgb * 32 + c0 + 1],       ahb[0], alb[0]);
            split_bf2(x[(rgb + 8) * 32 + c0],     x[(rgb + 8) * 32 + c0 + 1], ahb[1], alb[1]);
            split_bf2(x[rgb * 32 + c0 + 8],       x[rgb * 32 + c0 + 9],       ahb[2], alb[2]);
            split_bf2(x[(rgb + 8) * 32 + c0 + 8], x[(rgb + 8) * 32 + c0 + 9], ahb[3], alb[3]);
#pragma unroll
            for (int nb = 0; nb < 8; nb++) {
                float4 w = *reinterpret_cast<const float4*>(
                    s + W_B1 + ((kb * 8 + nb) * 32 + lane) * 4);
                uint32_t bh0 = __float_as_uint(w.x), bh1 = __float_as_uint(w.y);
                uint32_t bl0 = __float_as_uint(w.z), bl1 = __float_as_uint(w.w);
                mma16(d1a[nb], aha, bh0, bh1);
                mma16(d1b[nb], ahb, bh0, bh1);
                mma16(d1a[nb], ala, bh0, bh1);
                mma16(d1b[nb], alb, bh0, bh1);
                mma16(d1a[nb], aha, bl0, bl1);
                mma16(d1b[nb], ahb, bl0, bl1);
            }
        }
        biasact<8, 1>(d1a, s + E_BB1, lane);
        biasact<8, 1>(d1b, s + E_BB1, lane);
        float d2a_[4][4], d2b_[4][4];
        layer_stream2<4, 4>(s + W_B2, d1a, d1b, d2a_, d2b_, lane);
        biasact<4, 2>(d2a_, s + E_BB2, lane);
        biasact<4, 2>(d2b_, s + E_BB2, lane);
        float d3a[4][4], d3b[4][4];
        layer_stream2<2, 4>(s + W_B3, d2a_, d2b_, d3a, d3b, lane);
        biasact<4, 2>(d3a, s + E_BB3, lane);
        biasact<4, 2>(d3b, s + E_BB3, lane);
        float d4a[2][4], d4b[2][4];
        layer_stream2<2, 2>(s + W_B4, d3a, d3b, d4a, d4b, lane);
        biasact<2, 2>(d4a, s + E_BB4, lane);
        biasact<2, 2>(d4b, s + E_BB4, lane);
        // collapsed 16->1 dot, both halves
        float pa = 0.f, pa8 = 0.f, pb = 0.f, pb8 = 0.f;
#pragma unroll
        for (int nb = 0; nb < 2; nb++) {
            float w0 = s[E_WEFF + nb * 8 + 2 * q];
            float w1 = s[E_WEFF + nb * 8 + 2 * q + 1];
            pa  = fmaf(d4a[nb][0], w0, fmaf(d4a[nb][1], w1, pa));
            pa8 = fmaf(d4a[nb][2], w0, fmaf(d4a[nb][3], w1, pa8));
            pb  = fmaf(d4b[nb][0], w0, fmaf(d4b[nb][1], w1, pb));
            pb8 = fmaf(d4b[nb][2], w0, fmaf(d4b[nb][3], w1, pb8));
        }
        pa  += __shfl_xor_sync(0xffffffffu, pa, 1);
        pa  += __shfl_xor_sync(0xffffffffu, pa, 2);
        pa8 += __shfl_xor_sync(0xffffffffu, pa8, 1);
        pa8 += __shfl_xor_sync(0xffffffffu, pa8, 2);
        pb  += __shfl_xor_sync(0xffffffffu, pb, 1);
        pb  += __shfl_xor_sync(0xffffffffu, pb, 2);
        pb8 += __shfl_xor_sync(0xffffffffu, pb8, 1);
        pb8 += __shfl_xor_sync(0xffffffffu, pb8, 2);
        const float bO_a  = pa + s[E_BEFF];
        const float bO_a8 = pa8 + s[E_BEFF];
        const float bO_b  = pb + s[E_BEFF];
        const float bO_b8 = pb8 + s[E_BEFF];

        // ======== encoder A ========
        const float xsa  = x[rga * 32 + p];
        const float xsa8 = x[(rga + 8) * 32 + p];
        const float xsb  = x[rgb * 32 + p];
        const float xsb8 = x[(rgb + 8) * 32 + p];
        float dA2a[4][4], dA2b[4][4];
#pragma unroll
        for (int nb = 0; nb < 4; nb++) {
            dA2a[nb][0] = 0.f; dA2a[nb][1] = 0.f; dA2a[nb][2] = 0.f; dA2a[nb][3] = 0.f;
            dA2b[nb][0] = 0.f; dA2b[nb][1] = 0.f; dA2b[nb][2] = 0.f; dA2b[nb][3] = 0.f;
        }
#pragma unroll
        for (int kb = 0; kb < 4; kb++) {
            const int c0 = kb * 16 + 2 * q;
            float wA[4], bA[4];
            wA[0] = s[E_WA1 + c0];     bA[0] = s[E_BA1 + c0];
            wA[1] = s[E_WA1 + c0 + 1]; bA[1] = s[E_BA1 + c0 + 1];
            wA[2] = s[E_WA1 + c0 + 8]; bA[2] = s[E_BA1 + c0 + 8];
            wA[3] = s[E_WA1 + c0 + 9]; bA[3] = s[E_BA1 + c0 + 9];
            uint32_t aha[4], ala[4], ahb[4], alb[4];
            split_bf2(fmaxf(fmaf(wA[0], xsa,  bA[0]), 0.f),
                      fmaxf(fmaf(wA[1], xsa,  bA[1]), 0.f), aha[0], ala[0]);
            split_bf2(fmaxf(fmaf(wA[0], xsa8, bA[0]), 0.f),
                      fmaxf(fmaf(wA[1], xsa8, bA[1]), 0.f), aha[1], ala[1]);
            split_bf2(fmaxf(fmaf(wA[2], xsa,  bA[2]), 0.f),
                      fmaxf(fmaf(wA[3], xsa,  bA[3]), 0.f), aha[2], ala[2]);
            split_bf2(fmaxf(fmaf(wA[2], xsa8, bA[2]), 0.f),
                      fmaxf(fmaf(wA[3], xsa8, bA[3]), 0.f), aha[3], ala[3]);
            split_bf2(fmaxf(fmaf(wA[0], xsb,  bA[0]), 0.f),
                      fmaxf(fmaf(wA[1], xsb,  bA[1]), 0.f), ahb[0], alb[0]);
            split_bf2(fmaxf(fmaf(wA[0], xsb8, bA[0]), 0.f),
                      fmaxf(fmaf(wA[1], xsb8, bA[1]), 0.f), ahb[1], alb[1]);
            split_bf2(fmaxf(fmaf(wA[2], xsb,  bA[2]), 0.f),
                      fmaxf(fmaf(wA[3], xsb,  bA[3]), 0.f), ahb[2], alb[2]);
            split_bf2(fmaxf(fmaf(wA[2], xsb8, bA[2]), 0.f),
                      fmaxf(fmaf(wA[3], xsb8, bA[3]), 0.f), ahb[3], alb[3]);
#pragma unroll
            for (int nb = 0; nb < 4; nb++) {
                float4 w = *reinterpret_cast<const float4*>(
                    s + W_A2 + ((kb * 4 + nb) * 32 + lane) * 4);
                uint32_t bh0 = __float_as_uint(w.x), bh1 = __float_as_uint(w.y);
                uint32_t bl0 = __float_as_uint(w.z), bl1 = __float_as_uint(w.w);
                mma16(dA2a[nb], aha, bh0, bh1);
                mma16(dA2b[nb], ahb, bh0, bh1);
                mma16(dA2a[nb], ala, bh0, bh1);
                mma16(dA2b[nb], alb, bh0, bh1);
                mma16(dA2a[nb], aha, bl0, bl1);
                mma16(dA2b[nb], ahb, bl0, bl1);
            }
        }
        biasact<4, 2>(dA2a, s + E_BA2, lane);
        biasact<4, 2>(dA2b, s + E_BA2, lane);
        float dA3a[2][4], dA3b[2][4];
        layer_stream2<2, 2>(s + W_A3, dA2a, dA2b, dA3a, dA3b, lane);
        biasact<2, 2>(dA3a, s + E_BA3, lane);
        biasact<2, 2>(dA3b, s + E_BA3, lane);
        // A4 (16->8, tanh) + A5 (8->1), both halves
        float aO_a = s[E_BA5], aO_a8 = s[E_BA5];
        float aO_b = s[E_BA5], aO_b8 = s[E_BA5];
#pragma unroll
        for (int o = 0; o < 8; o++) {
            float sa = 0.f, sa8 = 0.f, sb = 0.f, sb8 = 0.f;
#pragma unroll
            for (int nb = 0; nb < 2; nb++) {
                int c0 = nb * 8 + 2 * q, c1 = c0 + 1;
                float w0 = s[E_WA4 + o * 16 + c0];
                float w1 = s[E_WA4 + o * 16 + c1];
                sa  = fmaf(dA3a[nb][0], w0, fmaf(dA3a[nb][1], w1, sa));
                sa8 = fmaf(dA3a[nb][2], w0, fmaf(dA3a[nb][3], w1, sa8));
                sb  = fmaf(dA3b[nb][0], w0, fmaf(dA3b[nb][1], w1, sb));
                sb8 = fmaf(dA3b[nb][2], w0, fmaf(dA3b[nb][3], w1, sb8));
            }
            sa  += __shfl_xor_sync(0xffffffffu, sa, 1);
            sa  += __shfl_xor_sync(0xffffffffu, sa, 2);
            sa8 += __shfl_xor_sync(0xffffffffu, sa8, 1);
            sa8 += __shfl_xor_sync(0xffffffffu, sa8, 2);
            sb  += __shfl_xor_sync(0xffffffffu, sb, 1);
            sb  += __shfl_xor_sync(0xffffffffu, sb, 2);
            sb8 += __shfl_xor_sync(0xffffffffu, sb8, 1);
            sb8 += __shfl_xor_sync(0xffffffffu, sb8, 2);
            const float w5 = s[E_WA5 + o], b4 = s[E_BA4 + o];
            aO_a  = fmaf(w5, fast_tanh(sa + b4), aO_a);
            aO_a8 = fmaf(w5, fast_tanh(sa8 + b4), aO_a8);
            aO_b  = fmaf(w5, fast_tanh(sb + b4), aO_b);
            aO_b8 = fmaf(w5, fast_tanh(sb8 + b4), aO_b8);
        }

        if (q == 0) {
            out[rga * 64 + 2 * p + 0] = aO_a;
            out[rga * 64 + 2 * p + 1] = bO_a;
            out[(rga + 8) * 64 + 2 * p + 0] = aO_a8;
            out[(rga + 8) * 64 + 2 * p + 1] = bO_a8;
            out[rgb * 64 + 2 * p + 0] = aO_b;
            out[rgb * 64 + 2 * p + 1] = bO_b;
            out[(rgb + 8) * 64 + 2 * p + 0] = aO_b8;
            out[(rgb + 8) * 64 + 2 * p + 1] = bO_b8;
        }
    }
}

extern "C" void kernel_launch(void* const* d_in, const int* in_sizes, int n_in,
                              void* d_out, int out_size) {
    const float* x   = (const float*)d_in[0];
    const float* Wa1 = (const float*)d_in[1];
    const float* ba1 = (const float*)d_in[2];
    const float* Wa2 = (const float*)d_in[3];
    const float* ba2 = (const float*)d_in[4];
    const float* Wa3 = (const float*)d_in[5];
    const float* ba3 = (const float*)d_in[6];
    const float* Wa4 = (const float*)d_in[7];
    const float* ba4 = (const float*)d_in[8];
    const float* Wa5 = (const float*)d_in[9];
    const float* ba5 = (const float*)d_in[10];
    const float* Wb1 = (const float*)d_in[11];
    const float* bb1 = (const float*)d_in[12];
    const float* Wb2 = (const float*)d_in[13];
    const float* bb2 = (const float*)d_in[14];
    const float* Wb3 = (const float*)d_in[15];
    const float* bb3 = (const float*)d_in[16];
    const float* Wb4 = (const float*)d_in[17];
    const float* bb4 = (const float*)d_in[18];
    const float* Wb5 = (const float*)d_in[19];
    const float* bb5 = (const float*)d_in[20];
    const float* Wb6 = (const float*)d_in[21];
    const float* bb6 = (const float*)d_in[22];
    float* out = (float*)d_out;

    const int nrows = in_sizes[0] / PFEAT;
    const size_t smemBytes = SMEM_FLOATS * sizeof(float);
    cudaFuncSetAttribute(mlp32_mma_kernel,
                         cudaFuncAttributeMaxDynamicSharedMemorySize,
                         (int)smemBytes);
    dim3 grid(CPF, PFEAT);
    mlp32_mma_kernel<<<grid, NTHREADS, smemBytes>>>(
        x, Wa1, ba1, Wa2, ba2, Wa3, ba3, Wa4, ba4, Wa5, ba5,
        Wb1, bb1, Wb2, bb2, Wb3, bb3, Wb4, bb4, Wb5, bb5, Wb6, bb6,
        out, nrows);
}

// round 16
// speedup vs baseline: 4.9193x; 1.4075x over previous
#include <cuda_runtime.h>
#include <cuda_bf16.h>
#include <cstdint>

#define NTHREADS 256
#define WARPS 8
#define PFEAT 32
#define CPF 9               // main: 288 CTAs (single wave at 2 CTA/SM)

#define TABN 8192
#define TAB_LO (-6.0f)
#define TAB_STEP (12.0f / (float)TABN)
#define TAB_INVSTEP ((float)TABN / 12.0f)

__device__ float g_atab[PFEAT * TABN];   // 1 MB scratch (static, allowed)

// ---- main-kernel smem float offsets (encoder B only) ----
#define W_B1 0        // KB2 NB8 -> 2048
#define W_B2 2048     // KB4 NB4 -> 2048
#define W_B3 4096     // KB2 NB4 -> 1024
#define W_B4 5120     // KB2 NB2 -> 512
#define E_BB1 5632
#define E_BB2 5696
#define E_BB3 5728
#define E_BB4 5760
#define E_WEFF 5776
#define E_BEFF 5792
#define SMEM_MAIN 5796

// ---- build-kernel smem float offsets (encoder A only) ----
#define W_A2 0        // KB4 NB4 -> 2048
#define W_A3 2048     // KB2 NB2 -> 512
#define T_WA1 2560
#define T_BA1 2624
#define T_BA2 2688
#define T_BA3 2720
#define T_WA4 2736
#define T_BA4 2864
#define T_WA5 2872
#define T_BA5 2880
#define SMEM_BUILD 2884

__device__ __forceinline__ float fast_tanh(float x) {
    float r; asm("tanh.approx.f32 %0, %1;" : "=f"(r) : "f"(x)); return r;
}
__device__ __forceinline__ uint32_t packbf(float v0, float v1) {
    uint32_t d;
    asm("cvt.rn.bf16x2.f32 %0, %1, %2;" : "=r"(d) : "f"(v1), "f"(v0));
    return d;
}
__device__ __forceinline__ void split_bf2(float v0, float v1,
                                          uint32_t& h, uint32_t& l) {
    uint32_t hp = packbf(v0, v1);
    float h0 = __uint_as_float(hp << 16);
    float h1 = __uint_as_float(hp & 0xffff0000u);
    h = hp;
    l = packbf(v0 - h0, v1 - h1);
}
__device__ __forceinline__ void mma16(float* d, const uint32_t* a,
                                      uint32_t b0, uint32_t b1) {
    asm volatile(
        "mma.sync.aligned.m16n8k16.row.col.f32.bf16.bf16.f32 "
        "{%0,%1,%2,%3}, {%4,%5,%6,%7}, {%8,%9}, {%0,%1,%2,%3};"
        : "+f"(d[0]), "+f"(d[1]), "+f"(d[2]), "+f"(d[3])
        : "r"(a[0]), "r"(a[1]), "r"(a[2]), "r"(a[3]), "r"(b0), "r"(b1));
}

template<int NB, int ACT>
__device__ __forceinline__ void biasact(float (*d)[4],
                                        const float* __restrict__ bias, int lane) {
    const int q = lane & 3;
#pragma unroll
    for (int nb = 0; nb < NB; nb++) {
        float b0 = bias[nb * 8 + 2 * q], b1 = bias[nb * 8 + 2 * q + 1];
        float v0 = d[nb][0] + b0, v1 = d[nb][1] + b1;
        float v2 = d[nb][2] + b0, v3 = d[nb][3] + b1;
        if (ACT == 1) { v0 = fmaxf(v0, 0.f); v1 = fmaxf(v1, 0.f);
                        v2 = fmaxf(v2, 0.f); v3 = fmaxf(v3, 0.f); }
        if (ACT == 2) { v0 = fast_tanh(v0); v1 = fast_tanh(v1);
                        v2 = fast_tanh(v2); v3 = fast_tanh(v3); }
        d[nb][0] = v0; d[nb][1] = v1; d[nb][2] = v2; d[nb][3] = v3;
    }
}

// two D blocks -> one bf16 A block (lane-identical, no shuffles)
__device__ __forceinline__ void d2a(const float* dj0, const float* dj1,
                                    uint32_t* ah, uint32_t* al) {
    split_bf2(dj0[0], dj0[1], ah[0], al[0]);
    split_bf2(dj0[2], dj0[3], ah[1], al[1]);
    split_bf2(dj1[0], dj1[1], ah[2], al[2]);
    split_bf2(dj1[2], dj1[3], ah[3], al[3]);
}

// streamed bf16 layer, TWO 16-row halves share every weight load
template<int KBB, int NB>
__device__ __forceinline__ void layer_stream2(const float* __restrict__ wp,
                                              const float (*dpa)[4],
                                              const float (*dpb)[4],
                                              float (*dna)[4], float (*dnb)[4],
                                              int lane) {
#pragma unroll
    for (int nb = 0; nb < NB; nb++) {
        dna[nb][0] = 0.f; dna[nb][1] = 0.f; dna[nb][2] = 0.f; dna[nb][3] = 0.f;
        dnb[nb][0] = 0.f; dnb[nb][1] = 0.f; dnb[nb][2] = 0.f; dnb[nb][3] = 0.f;
    }
#pragma unroll
    for (int j = 0; j < KBB; j++) {
        uint32_t aha[4], ala[4], ahb[4], alb[4];
        d2a(dpa[2 * j], dpa[2 * j + 1], aha, ala);
        d2a(dpb[2 * j], dpb[2 * j + 1], ahb, alb);
#pragma unroll
        for (int nb = 0; nb < NB; nb++) {
            float4 w = *reinterpret_cast<const float4*>(
                wp + ((j * NB + nb) * 32 + lane) * 4);
            uint32_t bh0 = __float_as_uint(w.x), bh1 = __float_as_uint(w.y);
            uint32_t bl0 = __float_as_uint(w.z), bl1 = __float_as_uint(w.w);
            mma16(dna[nb], aha, bh0, bh1);
            mma16(dnb[nb], ahb, bh0, bh1);
            mma16(dna[nb], ala, bh0, bh1);
            mma16(dnb[nb], alb, bh0, bh1);
            mma16(dna[nb], aha, bl0, bl1);
            mma16(dnb[nb], ahb, bl0, bl1);
        }
    }
}

// stage one layer's weights as bf16 hi/lo, m16n8k16 B layout
template<int IN, int OUT, bool LOO>
__device__ void stageL(float* wp, const float* __restrict__ W, int p, int tid) {
    constexpr int KB = IN / 16, NB = OUT / 8;
    for (int e = tid; e < KB * NB * 32; e += NTHREADS) {
        int blk = e >> 5, lane = e & 31;
        int kb = blk / NB, nb = blk % NB;
        int n = nb * 8 + (lane >> 2);
        int k0 = kb * 16 + 2 * (lane & 3);
        float w00, w01, w08, w09;
        if (LOO) {
            w00 = (k0 == p)     ? 0.f : W[n * 31 + (k0 < p ? k0 : k0 - 1)];
            w01 = (k0 + 1 == p) ? 0.f : W[n * 31 + (k0 + 1 < p ? k0 + 1 : k0)];
            w08 = (k0 + 8 == p) ? 0.f : W[n * 31 + (k0 + 8 < p ? k0 + 8 : k0 + 7)];
            w09 = (k0 + 9 == p) ? 0.f : W[n * 31 + (k0 + 9 < p ? k0 + 9 : k0 + 8)];
        } else {
            w00 = W[n * IN + k0];     w01 = W[n * IN + k0 + 1];
            w08 = W[n * IN + k0 + 8]; w09 = W[n * IN + k0 + 9];
        }
        uint32_t bh0, bl0, bh1, bl1;
        split_bf2(w00, w01, bh0, bl0);
        split_bf2(w08, w09, bh1, bl1);
        float4* dst = reinterpret_cast<float4*>(wp + (blk * 32 + lane) * 4);
        *dst = make_float4(__uint_as_float(bh0), __uint_as_float(bh1),
                           __uint_as_float(bl0), __uint_as_float(bl1));
    }
}

__device__ __forceinline__ void cpyf(float* dst, const float* __restrict__ src,
                                     int n, int tid) {
    for (int i = tid; i < n; i += NTHREADS) dst[i] = src[i];
}

// ======================= kernel 1: tabulate encoder A =======================
__global__ void __launch_bounds__(NTHREADS, 2)
build_atab_kernel(const float* __restrict__ Wa1, const float* __restrict__ ba1,
                  const float* __restrict__ Wa2, const float* __restrict__ ba2,
                  const float* __restrict__ Wa3, const float* __restrict__ ba3,
                  const float* __restrict__ Wa4, const float* __restrict__ ba4,
                  const float* __restrict__ Wa5, const float* __restrict__ ba5) {
    extern __shared__ float s[];
    const int p = blockIdx.y;
    const int tid = threadIdx.x;
    const int lane = tid & 31;
    const int warp = tid >> 5;
    const int q = lane & 3;

    stageL<64, 32, false>(s + W_A2, Wa2 + p * 32 * 64, p, tid);
    stageL<32, 16, false>(s + W_A3, Wa3 + p * 16 * 32, p, tid);
    cpyf(s + T_WA1, Wa1 + p * 64, 64, tid);
    cpyf(s + T_BA1, ba1 + p * 64, 64, tid);
    cpyf(s + T_BA2, ba2 + p * 32, 32, tid);
    cpyf(s + T_BA3, ba3 + p * 16, 16, tid);
    cpyf(s + T_WA4, Wa4 + p * 128, 128, tid);
    cpyf(s + T_BA4, ba4 + p * 8, 8, tid);
    cpyf(s + T_WA5, Wa5 + p * 8, 8, tid);
    if (tid == 0) s[T_BA5] = ba5[p];
    __syncthreads();

    const int NTT = TABN / 32;   // 256 tiles
    for (int t = blockIdx.x * WARPS + warp; t < NTT; t += 8 * WARPS) {
        const int ia = t * 32 + (lane >> 2);
        const float xsa  = fmaf((float)ia,        TAB_STEP, TAB_LO);
        const float xsa8 = fmaf((float)(ia + 8),  TAB_STEP, TAB_LO);
        const float xsb  = fmaf((float)(ia + 16), TAB_STEP, TAB_LO);
        const float xsb8 = fmaf((float)(ia + 24), TAB_STEP, TAB_LO);

        float dA2a[4][4], dA2b[4][4];
#pragma unroll
        for (int nb = 0; nb < 4; nb++) {
            dA2a[nb][0] = 0.f; dA2a[nb][1] = 0.f; dA2a[nb][2] = 0.f; dA2a[nb][3] = 0.f;
            dA2b[nb][0] = 0.f; dA2b[nb][1] = 0.f; dA2b[nb][2] = 0.f; dA2b[nb][3] = 0.f;
        }
#pragma unroll
        for (int kb = 0; kb < 4; kb++) {
            const int c0 = kb * 16 + 2 * q;
            float wA[4], bA[4];
            wA[0] = s[T_WA1 + c0];     bA[0] = s[T_BA1 + c0];
            wA[1] = s[T_WA1 + c0 + 1]; bA[1] = s[T_BA1 + c0 + 1];
            wA[2] = s[T_WA1 + c0 + 8]; bA[2] = s[T_BA1 + c0 + 8];
            wA[3] = s[T_WA1 + c0 + 9]; bA[3] = s[T_BA1 + c0 + 9];
            uint32_t aha[4], ala[4], ahb[4], alb[4];
            split_bf2(fmaxf(fmaf(wA[0], xsa,  bA[0]), 0.f),
                      fmaxf(fmaf(wA[1], xsa,  bA[1]), 0.f), aha[0], ala[0]);
            split_bf2(fmaxf(fmaf(wA[0], xsa8, bA[0]), 0.f),
                      fmaxf(fmaf(wA[1], xsa8, bA[1]), 0.f), aha[1], ala[1]);
            split_bf2(fmaxf(fmaf(wA[2], xsa,  bA[2]), 0.f),
                      fmaxf(fmaf(wA[3], xsa,  bA[3]), 0.f), aha[2], ala[2]);
            split_bf2(fmaxf(fmaf(wA[2], xsa8, bA[2]), 0.f),
                      fmaxf(fmaf(wA[3], xsa8, bA[3]), 0.f), aha[3], ala[3]);
            split_bf2(fmaxf(fmaf(wA[0], xsb,  bA[0]), 0.f),
                      fmaxf(fmaf(wA[1], xsb,  bA[1]), 0.f), ahb[0], alb[0]);
            split_bf2(fmaxf(fmaf(wA[0], xsb8, bA[0]), 0.f),
                      fmaxf(fmaf(wA[1], xsb8, bA[1]), 0.f), ahb[1], alb[1]);
            split_bf2(fmaxf(fmaf(wA[2], xsb,  bA[2]), 0.f),
                      fmaxf(fmaf(wA[3], xsb,  bA[3]), 0.f), ahb[2], alb[2]);
            split_bf2(fmaxf(fmaf(wA[2], xsb8, bA[2]), 0.f),
                      fmaxf(fmaf(wA[3], xsb8, bA[3]), 0.f), ahb[3], alb[3]);
#pragma unroll
            for (int nb = 0; nb < 4; nb++) {
                float4 w = *reinterpret_cast<const float4*>(
                    s + W_A2 + ((kb * 4 + nb) * 32 + lane) * 4);
                uint32_t bh0 = __float_as_uint(w.x), bh1 = __float_as_uint(w.y);
                uint32_t bl0 = __float_as_uint(w.z), bl1 = __float_as_uint(w.w);
                mma16(dA2a[nb], aha, bh0, bh1);
                mma16(dA2b[nb], ahb, bh0, bh1);
                mma16(dA2a[nb], ala, bh0, bh1);
                mma16(dA2b[nb], alb, bh0, bh1);
                mma16(dA2a[nb], aha, bl0, bl1);
                mma16(dA2b[nb], ahb, bl0, bl1);
            }
        }
        biasact<4, 2>(dA2a, s + T_BA2, lane);
        biasact<4, 2>(dA2b, s + T_BA2, lane);
        float dA3a[2][4], dA3b[2][4];
        layer_stream2<2, 2>(s + W_A3, dA2a, dA2b, dA3a, dA3b, lane);
        biasact<2, 2>(dA3a, s + T_BA3, lane);
        biasact<2, 2>(dA3b, s + T_BA3, lane);
        float aO_a = s[T_BA5], aO_a8 = s[T_BA5];
        float aO_b = s[T_BA5], aO_b8 = s[T_BA5];
#pragma unroll
        for (int o = 0; o < 8; o++) {
            float sa = 0.f, sa8 = 0.f, sb = 0.f, sb8 = 0.f;
#pragma unroll
            for (int nb = 0; nb < 2; nb++) {
                int c0 = nb * 8 + 2 * q, c1 = c0 + 1;
                float w0 = s[T_WA4 + o * 16 + c0];
                float w1 = s[T_WA4 + o * 16 + c1];
                sa  = fmaf(dA3a[nb][0], w0, fmaf(dA3a[nb][1], w1, sa));
                sa8 = fmaf(dA3a[nb][2], w0, fmaf(dA3a[nb][3], w1, sa8));
                sb  = fmaf(dA3b[nb][0], w0, fmaf(dA3b[nb][1], w1, sb));
                sb8 = fmaf(dA3b[nb][2], w0, fmaf(dA3b[nb][3], w1, sb8));
            }
            sa  += __shfl_xor_sync(0xffffffffu, sa, 1);
            sa  += __shfl_xor_sync(0xffffffffu, sa, 2);
            sa8 += __shfl_xor_sync(0xffffffffu, sa8, 1);
            sa8 += __shfl_xor_sync(0xffffffffu, sa8, 2);
            sb  += __shfl_xor_sync(0xffffffffu, sb, 1);
            sb  += __shfl_xor_sync(0xffffffffu, sb, 2);
            sb8 += __shfl_xor_sync(0xffffffffu, sb8, 1);
            sb8 += __shfl_xor_sync(0xffffffffu, sb8, 2);
            const float w5 = s[T_WA5 + o], b4 = s[T_BA4 + o];
            aO_a  = fmaf(w5, fast_tanh(sa + b4), aO_a);
            aO_a8 = fmaf(w5, fast_tanh(sa8 + b4), aO_a8);
            aO_b  = fmaf(w5, fast_tanh(sb + b4), aO_b);
            aO_b8 = fmaf(w5, fast_tanh(sb8 + b4), aO_b8);
        }
        if (q == 0) {
            float* tab = g_atab + p * TABN;
            tab[ia] = aO_a;
            tab[ia + 8] = aO_a8;
            tab[ia + 16] = aO_b;
            tab[ia + 24] = aO_b8;
        }
    }
}

// table lookup with linear interpolation
__device__ __forceinline__ float alook(const float* __restrict__ tab, float xs) {
    float t = (xs - TAB_LO) * TAB_INVSTEP;
    t = fminf(fmaxf(t, 0.0f), (float)(TABN - 1) - 0.001f);
    int i = (int)t;
    float f = t - (float)i;
    float v0 = __ldg(tab + i), v1 = __ldg(tab + i + 1);
    return fmaf(f, v1 - v0, v0);
}

// ======================= kernel 2: encoder B (MMA) + A lookup =======================
__global__ void __launch_bounds__(NTHREADS, 2)
mlp32_mma_kernel(const float* __restrict__ x,
                 const float* __restrict__ Wb1, const float* __restrict__ bb1,
                 const float* __restrict__ Wb2, const float* __restrict__ bb2,
                 const float* __restrict__ Wb3, const float* __restrict__ bb3,
                 const float* __restrict__ Wb4, const float* __restrict__ bb4,
                 const float* __restrict__ Wb5, const float* __restrict__ bb5,
                 const float* __restrict__ Wb6, const float* __restrict__ bb6,
                 float* __restrict__ out, int nrows) {
    extern __shared__ float s[];
    const int p = blockIdx.y;
    const int tid = threadIdx.x;
    const int lane = tid & 31;
    const int warp = tid >> 5;
    const int q = lane & 3;

    stageL<32, 64, true >(s + W_B1, Wb1 + p * 64 * 31, p, tid);
    stageL<64, 32, false>(s + W_B2, Wb2 + p * 32 * 64, p, tid);
    stageL<32, 32, false>(s + W_B3, Wb3 + p * 32 * 32, p, tid);
    stageL<32, 16, false>(s + W_B4, Wb4 + p * 16 * 32, p, tid);
    cpyf(s + E_BB1, bb1 + p * 64, 64, tid);
    cpyf(s + E_BB2, bb2 + p * 32, 32, tid);
    cpyf(s + E_BB3, bb3 + p * 32, 32, tid);
    cpyf(s + E_BB4, bb4 + p * 16, 16, tid);
    if (tid < 16) {
        float acc = 0.f;
        for (int o = 0; o < 8; o++)
            acc = fmaf(Wb6[p * 8 + o], Wb5[p * 128 + o * 16 + tid], acc);
        s[E_WEFF + tid] = acc;
    }
    if (tid == 0) {
        float acc = bb6[p];
        for (int o = 0; o < 8; o++)
            acc = fmaf(Wb6[p * 8 + o], bb5[p * 8 + o], acc);
        s[E_BEFF] = acc;
    }
    __syncthreads();

    const int NT = nrows >> 5;   // 32-row warp-tiles

    for (int t = blockIdx.x * WARPS + warp; t < NT; t += CPF * WARPS) {
        const int rga = t * 32 + (lane >> 2);
        const int rgb = rga + 16;

        // ---- encoder B : layer1 (32->64 relu), both halves ----
        float d1a[8][4], d1b[8][4];
#pragma unroll
        for (int nb = 0; nb < 8; nb++) {
            d1a[nb][0] = 0.f; d1a[nb][1] = 0.f; d1a[nb][2] = 0.f; d1a[nb][3] = 0.f;
            d1b[nb][0] = 0.f; d1b[nb][1] = 0.f; d1b[nb][2] = 0.f; d1b[nb][3] = 0.f;
        }
#pragma unroll
        for (int kb = 0; kb < 2; kb++) {
            const int c0 = kb * 16 + 2 * q;
            uint32_t aha[4], ala[4], ahb[4], alb[4];
            split_bf2(x[rga * 32 + c0],           x[rga * 32 + c0 + 1],       aha[0], ala[0]);
            split_bf2(x[(rga + 8) * 32 + c0],     x[(rga + 8) * 32 + c0 + 1], aha[1], ala[1]);
            split_bf2(x[rga * 32 + c0 + 8],       x[rga * 32 + c0 + 9],       aha[2], ala[2]);
            split_bf2(x[(rga + 8) * 32 + c0 + 8], x[(rga + 8) * 32 + c0 + 9], aha[3], ala[3]);
            split_bf2(x[rgb * 32 + c0],           x[rgb * 32 + c0 + 1],       ahb[0], alb[0]);
            split_bf2(x[(rgb + 8) * 32 + c0],     x[(rgb + 8) * 32 + c0 + 1], ahb[1], alb[1]);
            split_bf2(x[rgb * 32 + c0 + 8],       x[rgb * 32 + c0 + 9],       ahb[2], alb[2]);
            split_bf2(x[(rgb + 8) * 32 + c0 + 8], x[(rgb + 8) * 32 + c0 + 9], ahb[3], alb[3]);
#pragma unroll
            for (int nb = 0; nb < 8; nb++) {
                float4 w = *reinterpret_cast<const float4*>(
                    s + W_B1 + ((kb * 8 + nb) * 32 + lane) * 4);
                uint32_t bh0 = __float_as_uint(w.x), bh1 = __float_as_uint(w.y);
                uint32_t bl0 = __float_as_uint(w.z), bl1 = __float_as_uint(w.w);
                mma16(d1a[nb], aha, bh0, bh1);
                mma16(d1b[nb], ahb, bh0, bh1);
                mma16(d1a[nb], ala, bh0, bh1);
                mma16(d1b[nb], alb, bh0, bh1);
                mma16(d1a[nb], aha, bl0, bl1);
                mma16(d1b[nb], ahb, bl0, bl1);
            }
        }
        biasact<8, 1>(d1a, s + E_BB1, lane);
        biasact<8, 1>(d1b, s + E_BB1, lane);
        float d2a_[4][4], d2b_[4][4];
        layer_stream2<4, 4>(s + W_B2, d1a, d1b, d2a_, d2b_, lane);
        biasact<4, 2>(d2a_, s + E_BB2, lane);
        biasact<4, 2>(d2b_, s + E_BB2, lane);
        float d3a[4][4], d3b[4][4];
        layer_stream2<2, 4>(s + W_B3, d2a_, d2b_, d3a, d3b, lane);
        biasact<4, 2>(d3a, s + E_BB3, lane);
        biasact<4, 2>(d3b, s + E_BB3, lane);
        float d4a[2][4], d4b[2][4];
        layer_stream2<2, 2>(s + W_B4, d3a, d3b, d4a, d4b, lane);
        biasact<2, 2>(d4a, s + E_BB4, lane);
        biasact<2, 2>(d4b, s + E_BB4, lane);
        // collapsed 16->1 dot, both halves
        float pa = 0.f, pa8 = 0.f, pb = 0.f, pb8 = 0.f;
#pragma unroll
        for (int nb = 0; nb < 2; nb++) {
            float w0 = s[E_WEFF + nb * 8 + 2 * q];
            float w1 = s[E_WEFF + nb * 8 + 2 * q + 1];
            pa  = fmaf(d4a[nb][0], w0, fmaf(d4a[nb][1], w1, pa));
            pa8 = fmaf(d4a[nb][2], w0, fmaf(d4a[nb][3], w1, pa8));
            pb  = fmaf(d4b[nb][0], w0, fmaf(d4b[nb][1], w1, pb));
            pb8 = fmaf(d4b[nb][2], w0, fmaf(d4b[nb][3], w1, pb8));
        }
        pa  += __shfl_xor_sync(0xffffffffu, pa, 1);
        pa  += __shfl_xor_sync(0xffffffffu, pa, 2);
        pa8 += __shfl_xor_sync(0xffffffffu, pa8, 1);
        pa8 += __shfl_xor_sync(0xffffffffu, pa8, 2);
        pb  += __shfl_xor_sync(0xffffffffu, pb, 1);
        pb  += __shfl_xor_sync(0xffffffffu, pb, 2);
        pb8 += __shfl_xor_sync(0xffffffffu, pb8, 1);
        pb8 += __shfl_xor_sync(0xffffffffu, pb8, 2);

        if (q == 0) {
            const float beff = s[E_BEFF];
            const float* tab = g_atab + p * TABN;
            out[rga * 64 + 2 * p + 0] = alook(tab, x[rga * 32 + p]);
            out[rga * 64 + 2 * p + 1] = pa + beff;
            out[(rga + 8) * 64 + 2 * p + 0] = alook(tab, x[(rga + 8) * 32 + p]);
            out[(rga + 8) * 64 + 2 * p + 1] = pa8 + beff;
            out[rgb * 64 + 2 * p + 0] = alook(tab, x[rgb * 32 + p]);
            out[rgb * 64 + 2 * p + 1] = pb + beff;
            out[(rgb + 8) * 64 + 2 * p + 0] = alook(tab, x[(rgb + 8) * 32 + p]);
            out[(rgb + 8) * 64 + 2 * p + 1] = pb8 + beff;
        }
    }
}

extern "C" void kernel_launch(void* const* d_in, const int* in_sizes, int n_in,
                              void* d_out, int out_size) {
    const float* x   = (const float*)d_in[0];
    const float* Wa1 = (const float*)d_in[1];
    const float* ba1 = (const float*)d_in[2];
    const float* Wa2 = (const float*)d_in[3];
    const float* ba2 = (const float*)d_in[4];
    const float* Wa3 = (const float*)d_in[5];
    const float* ba3 = (const float*)d_in[6];
    const float* Wa4 = (const float*)d_in[7];
    const float* ba4 = (const float*)d_in[8];
    const float* Wa5 = (const float*)d_in[9];
    const float* ba5 = (const float*)d_in[10];
    const float* Wb1 = (const float*)d_in[11];
    const float* bb1 = (const float*)d_in[12];
    const float* Wb2 = (const float*)d_in[13];
    const float* bb2 = (const float*)d_in[14];
    const float* Wb3 = (const float*)d_in[15];
    const float* bb3 = (const float*)d_in[16];
    const float* Wb4 = (const float*)d_in[17];
    const float* bb4 = (const float*)d_in[18];
    const float* Wb5 = (const float*)d_in[19];
    const float* bb5 = (const float*)d_in[20];
    const float* Wb6 = (const float*)d_in[21];
    const float* bb6 = (const float*)d_in[22];
    float* out = (float*)d_out;

    const int nrows = in_sizes[0] / PFEAT;

    // kernel 1: tabulate encoder A per feature (8192 nodes over [-6, 6])
    dim3 gridT(8, PFEAT);
    build_atab_kernel<<<gridT, NTHREADS, SMEM_BUILD * sizeof(float)>>>(
        Wa1, ba1, Wa2, ba2, Wa3, ba3, Wa4, ba4, Wa5, ba5);

    // kernel 2: encoder B (MMA) + A table lookup
    dim3 grid(CPF, PFEAT);
    mlp32_mma_kernel<<<grid, NTHREADS, SMEM_MAIN * sizeof(float)>>>(
        x, Wb1, bb1, Wb2, bb2, Wb3, bb3, Wb4, bb4, Wb5, bb5, Wb6, bb6,
        out, nrows);
}